// round 1
// baseline (speedup 1.0000x reference)
#include <cuda_runtime.h>
#include <cuda_bf16.h>
#include <cstdint>

// ---------------- problem constants ----------------
#define BATCH    2
#define SEQLEN   2048
#define DMODEL   1024
#define DINNER   2048
#define DSTATE   16
#define DCONV    4
#define CHUNK    256
#define NCHUNK   (SEQLEN / CHUNK)          // 8
#define NTOK     (BATCH * SEQLEN)          // 4096
#define EPSF     1e-10f
#define LNEPS    (-23.025850929940457f)    // log(1e-10)

// ---------------- scratch (device globals: allocation-free) ----------------
__device__ float g_xz[NTOK * (2 * DINNER)];     // 64 MB : [xi | z]
__device__ float g_xc[NTOK * DINNER];           // 32 MB : conv+silu output
__device__ float g_delta[NTOK * DINNER];        // 32 MB
__device__ float g_Bb[NTOK * DSTATE];           // 256 KB
__device__ float g_Cc[NTOK * DSTATE];           // 256 KB
__device__ float g_y[NTOK * DINNER];            // 32 MB : y (pre-gate, then gated)
__device__ float g_hloc[BATCH * NCHUNK * DINNER * DSTATE];  // 2 MB
__device__ float g_Atot[BATCH * NCHUNK * DINNER * DSTATE];  // 2 MB
__device__ float g_h0  [BATCH * NCHUNK * DINNER * DSTATE];  // 2 MB

// ---------------- fp32 SIMT GEMM: C[M,N] = A[M,K] * B[N,K]^T ----------------
// BM=BN=64, BK=16, 256 threads, 4x4 per thread. All dims multiples of tile.
__global__ __launch_bounds__(256)
void gemm_nt64(const float* __restrict__ A, const float* __restrict__ B,
               float* __restrict__ C, int M, int N, int K)
{
    __shared__ __align__(16) float As[16][68];
    __shared__ __align__(16) float Bs[16][68];

    const int tid = threadIdx.x;
    const int tx = tid & 15;        // 0..15 (N dir)
    const int ty = tid >> 4;        // 0..15 (M dir)
    const int lr = tid >> 2;        // load row 0..63
    const int lk = (tid & 3) << 2;  // load k   0,4,8,12

    const float* Ab = A + (size_t)(blockIdx.y * 64) * K;
    const float* Bb = B + (size_t)(blockIdx.x * 64) * K;
    float* Cb = C + (size_t)(blockIdx.y * 64) * N + blockIdx.x * 64;

    float acc[4][4];
#pragma unroll
    for (int i = 0; i < 4; i++)
#pragma unroll
        for (int j = 0; j < 4; j++) acc[i][j] = 0.f;

    for (int k0 = 0; k0 < K; k0 += 16) {
        float4 a4 = *(const float4*)(Ab + (size_t)lr * K + k0 + lk);
        float4 b4 = *(const float4*)(Bb + (size_t)lr * K + k0 + lk);
        As[lk + 0][lr] = a4.x; As[lk + 1][lr] = a4.y;
        As[lk + 2][lr] = a4.z; As[lk + 3][lr] = a4.w;
        Bs[lk + 0][lr] = b4.x; Bs[lk + 1][lr] = b4.y;
        Bs[lk + 2][lr] = b4.z; Bs[lk + 3][lr] = b4.w;
        __syncthreads();
#pragma unroll
        for (int kk = 0; kk < 16; kk++) {
            float4 ra = *(const float4*)(&As[kk][ty << 2]);
            float4 rb = *(const float4*)(&Bs[kk][tx << 2]);
            acc[0][0] = fmaf(ra.x, rb.x, acc[0][0]);
            acc[0][1] = fmaf(ra.x, rb.y, acc[0][1]);
            acc[0][2] = fmaf(ra.x, rb.z, acc[0][2]);
            acc[0][3] = fmaf(ra.x, rb.w, acc[0][3]);
            acc[1][0] = fmaf(ra.y, rb.x, acc[1][0]);
            acc[1][1] = fmaf(ra.y, rb.y, acc[1][1]);
            acc[1][2] = fmaf(ra.y, rb.z, acc[1][2]);
            acc[1][3] = fmaf(ra.y, rb.w, acc[1][3]);
            acc[2][0] = fmaf(ra.z, rb.x, acc[2][0]);
            acc[2][1] = fmaf(ra.z, rb.y, acc[2][1]);
            acc[2][2] = fmaf(ra.z, rb.z, acc[2][2]);
            acc[2][3] = fmaf(ra.z, rb.w, acc[2][3]);
            acc[3][0] = fmaf(ra.w, rb.x, acc[3][0]);
            acc[3][1] = fmaf(ra.w, rb.y, acc[3][1]);
            acc[3][2] = fmaf(ra.w, rb.z, acc[3][2]);
            acc[3][3] = fmaf(ra.w, rb.w, acc[3][3]);
        }
        __syncthreads();
    }
#pragma unroll
    for (int i = 0; i < 4; i++) {
        float4 o = make_float4(acc[i][0], acc[i][1], acc[i][2], acc[i][3]);
        *(float4*)(Cb + (size_t)(ty * 4 + i) * N + tx * 4) = o;
    }
}

// ---------------- conv1d + silu + x_proj + delta/B/C ----------------
// one block per token m = b*2048+t; 256 threads; each thread 8 channels
__global__ __launch_bounds__(256)
void conv_proj_kernel(const float* __restrict__ conv_w,
                      const float* __restrict__ conv_b,
                      const float* __restrict__ xpw,    // (33, 2048)
                      const float* __restrict__ dt_w,   // (2048,1)
                      const float* __restrict__ dt_b)   // (2048,)
{
    const int m = blockIdx.x;
    const int b = m >> 11;
    const int t = m & 2047;
    const int tid = threadIdx.x;
    const int lane = tid & 31;
    const int warp = tid >> 5;

    __shared__ float red[8][33];
    __shared__ float xps[33];

    float p[33];
#pragma unroll
    for (int j = 0; j < 33; j++) p[j] = 0.f;

#pragma unroll
    for (int jd = 0; jd < 8; jd++) {
        const int d = tid + jd * 256;
        float acc = conv_b[d];
#pragma unroll
        for (int k = 0; k < DCONV; k++) {
            int tt = t - (DCONV - 1) + k;
            float xv = (tt >= 0) ? g_xz[(size_t)(b * SEQLEN + tt) * (2 * DINNER) + d] : 0.f;
            acc = fmaf(conv_w[d * DCONV + k], xv, acc);
        }
        // silu (accurate exp; cold path)
        float xcv = acc / (1.f + expf(-acc));
        g_xc[(size_t)m * DINNER + d] = xcv;
#pragma unroll
        for (int j = 0; j < 33; j++)
            p[j] = fmaf(xcv, xpw[j * DINNER + d], p[j]);
    }
    // warp reduce each of 33 partials
#pragma unroll
    for (int j = 0; j < 33; j++) {
#pragma unroll
        for (int off = 16; off > 0; off >>= 1)
            p[j] += __shfl_down_sync(0xffffffffu, p[j], off);
    }
    if (lane == 0) {
#pragma unroll
        for (int j = 0; j < 33; j++) red[warp][j] = p[j];
    }
    __syncthreads();
    if (tid < 33) {
        float s = 0.f;
#pragma unroll
        for (int w = 0; w < 8; w++) s += red[w][tid];
        xps[tid] = s;
    }
    __syncthreads();

    const float xp0 = xps[0];
#pragma unroll
    for (int jd = 0; jd < 8; jd++) {
        const int d = tid + jd * 256;
        float u = fmaf(xp0, dt_w[d], dt_b[d]);
        // softplus = max(u,0) + log1p(exp(-|u|))
        float sp = fmaxf(u, 0.f) + log1pf(expf(-fabsf(u)));
        g_delta[(size_t)m * DINNER + d] = sp;
    }
    if (tid < DSTATE)            g_Bb[m * DSTATE + tid] = xps[1 + tid];
    else if (tid < 2 * DSTATE)   g_Cc[m * DSTATE + (tid - DSTATE)] = xps[1 + tid];
}

// ---------------- scan pass A: per-chunk local recurrence (h0 = 0) ----------
// grid: (8 dgroups, 8 chunks, 2 batch), 256 threads; thread owns one channel d
__global__ __launch_bounds__(256)
void scanA_kernel(const float* __restrict__ A_log,
                  const float* __restrict__ D_param)
{
    const int d = blockIdx.x * 256 + threadIdx.x;
    const int c = blockIdx.y;
    const int b = blockIdx.z;
    const int m0 = b * SEQLEN + c * CHUNK;

    __shared__ float Bs[CHUNK * DSTATE];
    __shared__ float Cs[CHUNK * DSTATE];
    {
        const float4* gb = (const float4*)(g_Bb + (size_t)m0 * DSTATE);
        const float4* gc = (const float4*)(g_Cc + (size_t)m0 * DSTATE);
        for (int i = threadIdx.x; i < CHUNK * DSTATE / 4; i += 256) {
            ((float4*)Bs)[i] = gb[i];
            ((float4*)Cs)[i] = gc[i];
        }
    }

    float Areg[DSTATE];
#pragma unroll
    for (int s = 0; s < DSTATE; s++) Areg[s] = -expf(A_log[s]);
    const float Dd = D_param[d];
    __syncthreads();

    float L[DSTATE], W[DSTATE], E[DSTATE], H[DSTATE];
#pragma unroll
    for (int s = 0; s < DSTATE; s++) { L[s] = 0.f; W[s] = 0.f; E[s] = 1.f; H[s] = 0.f; }

    for (int t = 0; t < CHUNK; t++) {
        const size_t idx = (size_t)(m0 + t) * DINNER + d;
        const float dl  = g_delta[idx];
        const float xcv = g_xc[idx];
        const float dx  = dl * xcv;
        float y = Dd * xcv;
#pragma unroll
        for (int s = 0; s < DSTATE; s++) {
            float la = fmaxf(dl * Areg[s], LNEPS);
            L[s] += la;
            float en = __expf(L[s]);                       // A_cum[t]
            float bx = dx * Bs[t * DSTATE + s];
            W[s] += __fdividef(bx, fmaxf(E[s], EPSF));     // / max(A_cum_sh, EPS)
            float h = E[s] * W[s];                         // A_cum[t]/A_bar = exp(L_{t-1})
            H[s] = h;
            y = fmaf(Cs[t * DSTATE + s], h, y);
            E[s] = en;
        }
        g_y[idx] = y;
    }
    // chunk summaries
    const size_t o = ((size_t)(b * NCHUNK + c) * DINNER + d) * DSTATE;
#pragma unroll
    for (int s = 0; s < DSTATE; s++) {
        g_hloc[o + s] = H[s];
        g_Atot[o + s] = E[s];
    }
}

// ---------------- chunk carry: h0_{c+1} = hloc_c + h0_c * Atot_c ------------
__global__ __launch_bounds__(256)
void carry_kernel()
{
    const int i = blockIdx.x * 256 + threadIdx.x;     // over b*d*s = 65536
    const int s = i & (DSTATE - 1);
    const int d = (i >> 4) & (DINNER - 1);
    const int b = i >> 15;
    float h = 0.f;
#pragma unroll
    for (int c = 0; c < NCHUNK; c++) {
        const size_t o = ((size_t)(b * NCHUNK + c) * DINNER + d) * DSTATE + s;
        g_h0[o] = h;
        h = g_hloc[o] + h * g_Atot[o];
    }
}

// ---------------- scan pass B: + C·h0·A_cum, then silu(z) gate --------------
__global__ __launch_bounds__(256)
void scanB_kernel(const float* __restrict__ A_log)
{
    const int d = blockIdx.x * 256 + threadIdx.x;
    const int c = blockIdx.y;
    const int b = blockIdx.z;
    const int m0 = b * SEQLEN + c * CHUNK;

    __shared__ float Cs[CHUNK * DSTATE];
    {
        const float4* gc = (const float4*)(g_Cc + (size_t)m0 * DSTATE);
        for (int i = threadIdx.x; i < CHUNK * DSTATE / 4; i += 256)
            ((float4*)Cs)[i] = gc[i];
    }

    float Areg[DSTATE], h0r[DSTATE], L[DSTATE];
    const size_t o = ((size_t)(b * NCHUNK + c) * DINNER + d) * DSTATE;
    bool any = false;
#pragma unroll
    for (int s = 0; s < DSTATE; s++) {
        Areg[s] = -expf(A_log[s]);
        h0r[s] = g_h0[o + s];
        L[s] = 0.f;
        any = any || (h0r[s] != 0.f);
    }
    __syncthreads();

    for (int t = 0; t < CHUNK; t++) {
        const size_t idx = (size_t)(m0 + t) * DINNER + d;
        float y = g_y[idx];
        if (any) {
            const float dl = g_delta[idx];
            float corr = 0.f;
#pragma unroll
            for (int s = 0; s < DSTATE; s++) {
                float la = fmaxf(dl * Areg[s], LNEPS);
                L[s] += la;
                corr = fmaf(h0r[s] * Cs[t * DSTATE + s], __expf(L[s]), corr);
            }
            y += corr;
        }
        // gate: y *= silu(z)
        const float zv = g_xz[(size_t)(m0 + t) * (2 * DINNER) + DINNER + d];
        const float sig = 1.f / (1.f + __expf(-zv));
        g_y[idx] = y * (zv * sig);
    }
}

// ---------------- launch ----------------
extern "C" void kernel_launch(void* const* d_in, const int* in_sizes, int n_in,
                              void* d_out, int out_size)
{
    const float* x       = (const float*)d_in[0];
    const float* in_w    = (const float*)d_in[1];
    const float* conv_w  = (const float*)d_in[2];
    const float* conv_b  = (const float*)d_in[3];
    const float* xpw     = (const float*)d_in[4];
    const float* dt_w    = (const float*)d_in[5];
    const float* dt_b    = (const float*)d_in[6];
    const float* A_log   = (const float*)d_in[7];
    const float* D_param = (const float*)d_in[8];
    const float* out_w   = (const float*)d_in[9];
    float* out           = (float*)d_out;

    float *p_xz, *p_y;
    cudaGetSymbolAddress((void**)&p_xz, g_xz);
    cudaGetSymbolAddress((void**)&p_y,  g_y);

    // 1) xz = x @ in_proj_w^T   (M=4096, N=4096, K=1024)
    {
        dim3 grid((2 * DINNER) / 64, NTOK / 64);
        gemm_nt64<<<grid, 256>>>(x, in_w, p_xz, NTOK, 2 * DINNER, DMODEL);
    }
    // 2) conv + silu + x_proj + delta/B/C
    conv_proj_kernel<<<NTOK, 256>>>(conv_w, conv_b, xpw, dt_w, dt_b);
    // 3) per-chunk local scan
    {
        dim3 grid(DINNER / 256, NCHUNK, BATCH);
        scanA_kernel<<<grid, 256>>>(A_log, D_param);
    }
    // 4) chunk carry
    carry_kernel<<<(BATCH * DINNER * DSTATE) / 256, 256>>>();
    // 5) carry correction + gate
    {
        dim3 grid(DINNER / 256, NCHUNK, BATCH);
        scanB_kernel<<<grid, 256>>>(A_log);
    }
    // 6) out = y @ out_proj_w^T   (M=4096, N=1024, K=2048)
    {
        dim3 grid(DMODEL / 64, NTOK / 64);
        gemm_nt64<<<grid, 256>>>(p_y, out_w, out, NTOK, DMODEL, DINNER);
    }
}

// round 2
// speedup vs baseline: 1.6587x; 1.6587x over previous
#include <cuda_runtime.h>
#include <cuda_bf16.h>
#include <cstdint>

// ---------------- problem constants ----------------
#define BATCH    2
#define SEQLEN   2048
#define DMODEL   1024
#define DINNER   2048
#define DSTATE   16
#define DCONV    4
#define CHUNK    256
#define NCHUNK   (SEQLEN / CHUNK)          // 8
#define NTOK     (BATCH * SEQLEN)          // 4096
#define EPSF     1e-10f
#define LNEPS    (-23.025850929940457f)    // log(1e-10)

// ---------------- scratch (device globals: allocation-free) ----------------
__device__ float g_xz[NTOK * (2 * DINNER)];     // 64 MB : [xi | z]
__device__ float g_xc[NTOK * DINNER];           // 32 MB : conv+silu output
__device__ float g_delta[NTOK * DINNER];        // 32 MB
__device__ float g_Bb[NTOK * DSTATE];           // 256 KB
__device__ float g_Cc[NTOK * DSTATE];           // 256 KB
__device__ float g_y[NTOK * DINNER];            // 32 MB : y (pre-gate, then gated)
__device__ float g_hloc[BATCH * NCHUNK * DINNER * DSTATE];  // 2 MB
__device__ float g_Atot[BATCH * NCHUNK * DINNER * DSTATE];  // 2 MB
__device__ float g_h0  [BATCH * NCHUNK * DINNER * DSTATE];  // 2 MB

// bf16 split-GEMM operands: A' = [hi|lo|hi], B' = [hi|hi|lo] along K
__device__ __nv_bfloat16 g_Xbig [NTOK   * 3 * DMODEL];   // 25 MB
__device__ __nv_bfloat16 g_W1big[(2*DINNER) * 3 * DMODEL]; // 25 MB
__device__ __nv_bfloat16 g_Ybig [NTOK   * 3 * DINNER];   // 50 MB
__device__ __nv_bfloat16 g_W2big[DMODEL * 3 * DINNER];   // 12.6 MB

// ---------------- mma helpers ----------------
__device__ __forceinline__ uint32_t smem_u32(const void* p) {
    return (uint32_t)__cvta_generic_to_shared(p);
}
__device__ __forceinline__ void ldsm_x4(uint32_t& r0, uint32_t& r1,
                                        uint32_t& r2, uint32_t& r3, uint32_t addr) {
    asm volatile("ldmatrix.sync.aligned.m8n8.x4.shared.b16 {%0,%1,%2,%3}, [%4];"
                 : "=r"(r0), "=r"(r1), "=r"(r2), "=r"(r3) : "r"(addr));
}
__device__ __forceinline__ void mma_bf16(float* c, const uint32_t* a, const uint32_t* b) {
    asm volatile("mma.sync.aligned.m16n8k16.row.col.f32.bf16.bf16.f32 "
                 "{%0,%1,%2,%3}, {%4,%5,%6,%7}, {%8,%9}, {%0,%1,%2,%3};"
                 : "+f"(c[0]), "+f"(c[1]), "+f"(c[2]), "+f"(c[3])
                 : "r"(a[0]), "r"(a[1]), "r"(a[2]), "r"(a[3]), "r"(b[0]), "r"(b[1]));
}

// ---------------- fp32 -> bf16 hi/lo triple pack ----------------
// mode 0: [hi | lo | hi] (A side)   mode 1: [hi | hi | lo] (B side)
__global__ __launch_bounds__(256)
void pack3_kernel(const float* __restrict__ src, __nv_bfloat16* __restrict__ dst,
                  int K, int mode)
{
    const int g = blockIdx.x * 256 + threadIdx.x;
    const int kq = K >> 2;
    const int r = g / kq;
    const int k4 = (g - r * kq) << 2;
    float4 v = *(const float4*)(src + (size_t)r * K + k4);
    float vv[4] = {v.x, v.y, v.z, v.w};
    __nv_bfloat16 h[4], l[4];
#pragma unroll
    for (int i = 0; i < 4; i++) {
        h[i] = __float2bfloat16(vv[i]);
        l[i] = __float2bfloat16(vv[i] - __bfloat162float(h[i]));
    }
    __nv_bfloat16* base = dst + (size_t)r * 3 * K;
    *(uint2*)&base[k4]           = *(uint2*)h;
    *(uint2*)&base[K + k4]       = mode ? *(uint2*)h : *(uint2*)l;
    *(uint2*)&base[2 * K + k4]   = mode ? *(uint2*)l : *(uint2*)h;
}

// ---------------- bf16 tensor-core GEMM: C[M,N] = A[M,K] * B[N,K]^T --------
// 128x128 block tile, BK=32, 8 warps (4 along M x 2 along N), warp tile 32x64
#define BKP 40
__global__ __launch_bounds__(256)
void gemm_bf16_nt(const __nv_bfloat16* __restrict__ A,
                  const __nv_bfloat16* __restrict__ B,
                  float* __restrict__ C, int M, int N, int K)
{
    __shared__ __align__(16) __nv_bfloat16 As[128][BKP];
    __shared__ __align__(16) __nv_bfloat16 Bs[128][BKP];

    const int tid  = threadIdx.x;
    const int warp = tid >> 5, lane = tid & 31;
    const int wm = (warp & 3) << 5;       // warp M offset (0..96)
    const int wn = (warp >> 2) << 6;      // warp N offset (0 or 64)
    const size_t bM = (size_t)blockIdx.y * 128;
    const size_t bN = (size_t)blockIdx.x * 128;

    float acc[2][8][4];
#pragma unroll
    for (int i = 0; i < 2; i++)
#pragma unroll
        for (int j = 0; j < 8; j++)
#pragma unroll
            for (int q = 0; q < 4; q++) acc[i][j][q] = 0.f;

    const int lrow  = lane & 15;
    const int lcolo = (lane >> 4) << 3;
    const int ldr   = tid >> 2;      // 0..63
    const int slot  = tid & 3;       // 0..3  (8 bf16 each)

    for (int k0 = 0; k0 < K; k0 += 32) {
        uint4 a0 = *(const uint4*)(A + (bM + ldr)      * (size_t)K + k0 + slot * 8);
        uint4 a1 = *(const uint4*)(A + (bM + 64 + ldr) * (size_t)K + k0 + slot * 8);
        uint4 b0 = *(const uint4*)(B + (bN + ldr)      * (size_t)K + k0 + slot * 8);
        uint4 b1 = *(const uint4*)(B + (bN + 64 + ldr) * (size_t)K + k0 + slot * 8);
        __syncthreads();
        *(uint4*)&As[ldr][slot * 8]      = a0;
        *(uint4*)&As[64 + ldr][slot * 8] = a1;
        *(uint4*)&Bs[ldr][slot * 8]      = b0;
        *(uint4*)&Bs[64 + ldr][slot * 8] = b1;
        __syncthreads();
#pragma unroll
        for (int kk = 0; kk < 32; kk += 16) {
            uint32_t af[2][4], bf[8][2];
#pragma unroll
            for (int i = 0; i < 2; i++)
                ldsm_x4(af[i][0], af[i][1], af[i][2], af[i][3],
                        smem_u32(&As[wm + i * 16 + lrow][kk + lcolo]));
#pragma unroll
            for (int j = 0; j < 4; j++) {
                uint32_t r0, r1, r2, r3;
                ldsm_x4(r0, r1, r2, r3,
                        smem_u32(&Bs[wn + j * 16 + lrow][kk + lcolo]));
                bf[2 * j][0] = r0; bf[2 * j + 1][0] = r1;
                bf[2 * j][1] = r2; bf[2 * j + 1][1] = r3;
            }
#pragma unroll
            for (int i = 0; i < 2; i++)
#pragma unroll
                for (int j = 0; j < 8; j++)
                    mma_bf16(acc[i][j], af[i], bf[j]);
        }
    }
#pragma unroll
    for (int i = 0; i < 2; i++) {
        const size_t rbase = bM + wm + i * 16 + (lane >> 2);
#pragma unroll
        for (int j = 0; j < 8; j++) {
            const size_t col = bN + wn + j * 8 + (lane & 3) * 2;
            *(float2*)&C[rbase * N + col]       = make_float2(acc[i][j][0], acc[i][j][1]);
            *(float2*)&C[(rbase + 8) * N + col] = make_float2(acc[i][j][2], acc[i][j][3]);
        }
    }
}

// ---------------- conv1d + silu + x_proj + delta/B/C ----------------
__global__ __launch_bounds__(256)
void conv_proj_kernel(const float* __restrict__ conv_w,
                      const float* __restrict__ conv_b,
                      const float* __restrict__ xpw,    // (33, 2048)
                      const float* __restrict__ dt_w,   // (2048,1)
                      const float* __restrict__ dt_b)   // (2048,)
{
    const int m = blockIdx.x;
    const int b = m >> 11;
    const int t = m & 2047;
    const int tid = threadIdx.x;
    const int lane = tid & 31;
    const int warp = tid >> 5;

    __shared__ float red[8][33];
    __shared__ float xps[33];

    float p[33];
#pragma unroll
    for (int j = 0; j < 33; j++) p[j] = 0.f;

#pragma unroll
    for (int jd = 0; jd < 8; jd++) {
        const int d = tid + jd * 256;
        float acc = conv_b[d];
#pragma unroll
        for (int k = 0; k < DCONV; k++) {
            int tt = t - (DCONV - 1) + k;
            float xv = (tt >= 0) ? g_xz[(size_t)(b * SEQLEN + tt) * (2 * DINNER) + d] : 0.f;
            acc = fmaf(conv_w[d * DCONV + k], xv, acc);
        }
        float xcv = acc / (1.f + expf(-acc));
        g_xc[(size_t)m * DINNER + d] = xcv;
#pragma unroll
        for (int j = 0; j < 33; j++)
            p[j] = fmaf(xcv, xpw[j * DINNER + d], p[j]);
    }
#pragma unroll
    for (int j = 0; j < 33; j++) {
#pragma unroll
        for (int off = 16; off > 0; off >>= 1)
            p[j] += __shfl_down_sync(0xffffffffu, p[j], off);
    }
    if (lane == 0) {
#pragma unroll
        for (int j = 0; j < 33; j++) red[warp][j] = p[j];
    }
    __syncthreads();
    if (tid < 33) {
        float s = 0.f;
#pragma unroll
        for (int w = 0; w < 8; w++) s += red[w][tid];
        xps[tid] = s;
    }
    __syncthreads();

    const float xp0 = xps[0];
#pragma unroll
    for (int jd = 0; jd < 8; jd++) {
        const int d = tid + jd * 256;
        float u = fmaf(xp0, dt_w[d], dt_b[d]);
        float sp = fmaxf(u, 0.f) + log1pf(expf(-fabsf(u)));
        g_delta[(size_t)m * DINNER + d] = sp;
    }
    if (tid < DSTATE)            g_Bb[m * DSTATE + tid] = xps[1 + tid];
    else if (tid < 2 * DSTATE)   g_Cc[m * DSTATE + (tid - DSTATE)] = xps[1 + tid];
}

// ---------------- scan pass A: per-chunk local recurrence (h0 = 0) ----------
__global__ __launch_bounds__(256)
void scanA_kernel(const float* __restrict__ A_log,
                  const float* __restrict__ D_param)
{
    const int d = blockIdx.x * 256 + threadIdx.x;
    const int c = blockIdx.y;
    const int b = blockIdx.z;
    const int m0 = b * SEQLEN + c * CHUNK;

    __shared__ float Bs[CHUNK * DSTATE];
    __shared__ float Cs[CHUNK * DSTATE];
    {
        const float4* gb = (const float4*)(g_Bb + (size_t)m0 * DSTATE);
        const float4* gc = (const float4*)(g_Cc + (size_t)m0 * DSTATE);
        for (int i = threadIdx.x; i < CHUNK * DSTATE / 4; i += 256) {
            ((float4*)Bs)[i] = gb[i];
            ((float4*)Cs)[i] = gc[i];
        }
    }

    float Areg[DSTATE];
#pragma unroll
    for (int s = 0; s < DSTATE; s++) Areg[s] = -expf(A_log[s]);
    const float Dd = D_param[d];
    __syncthreads();

    float L[DSTATE], W[DSTATE], E[DSTATE], H[DSTATE];
#pragma unroll
    for (int s = 0; s < DSTATE; s++) { L[s] = 0.f; W[s] = 0.f; E[s] = 1.f; H[s] = 0.f; }

    for (int t = 0; t < CHUNK; t++) {
        const size_t idx = (size_t)(m0 + t) * DINNER + d;
        const float dl  = g_delta[idx];
        const float xcv = g_xc[idx];
        const float dx  = dl * xcv;
        float y = Dd * xcv;
#pragma unroll
        for (int s = 0; s < DSTATE; s++) {
            float la = fmaxf(dl * Areg[s], LNEPS);
            L[s] += la;
            float en = __expf(L[s]);
            float bx = dx * Bs[t * DSTATE + s];
            W[s] += __fdividef(bx, fmaxf(E[s], EPSF));
            float h = E[s] * W[s];
            H[s] = h;
            y = fmaf(Cs[t * DSTATE + s], h, y);
            E[s] = en;
        }
        g_y[idx] = y;
    }
    const size_t o = ((size_t)(b * NCHUNK + c) * DINNER + d) * DSTATE;
#pragma unroll
    for (int s = 0; s < DSTATE; s++) {
        g_hloc[o + s] = H[s];
        g_Atot[o + s] = E[s];
    }
}

// ---------------- chunk carry ----------------
__global__ __launch_bounds__(256)
void carry_kernel()
{
    const int i = blockIdx.x * 256 + threadIdx.x;
    const int s = i & (DSTATE - 1);
    const int d = (i >> 4) & (DINNER - 1);
    const int b = i >> 15;
    float h = 0.f;
#pragma unroll
    for (int c = 0; c < NCHUNK; c++) {
        const size_t o = ((size_t)(b * NCHUNK + c) * DINNER + d) * DSTATE + s;
        g_h0[o] = h;
        h = g_hloc[o] + h * g_Atot[o];
    }
}

// ---------------- scan pass B: + C·h0·A_cum, then silu(z) gate --------------
__global__ __launch_bounds__(256)
void scanB_kernel(const float* __restrict__ A_log)
{
    const int d = blockIdx.x * 256 + threadIdx.x;
    const int c = blockIdx.y;
    const int b = blockIdx.z;
    const int m0 = b * SEQLEN + c * CHUNK;

    __shared__ float Cs[CHUNK * DSTATE];
    {
        const float4* gc = (const float4*)(g_Cc + (size_t)m0 * DSTATE);
        for (int i = threadIdx.x; i < CHUNK * DSTATE / 4; i += 256)
            ((float4*)Cs)[i] = gc[i];
    }

    float Areg[DSTATE], h0r[DSTATE], L[DSTATE];
    const size_t o = ((size_t)(b * NCHUNK + c) * DINNER + d) * DSTATE;
    bool any = false;
#pragma unroll
    for (int s = 0; s < DSTATE; s++) {
        Areg[s] = -expf(A_log[s]);
        h0r[s] = g_h0[o + s];
        L[s] = 0.f;
        any = any || (h0r[s] != 0.f);
    }
    __syncthreads();

    for (int t = 0; t < CHUNK; t++) {
        const size_t idx = (size_t)(m0 + t) * DINNER + d;
        float y = g_y[idx];
        if (any) {
            const float dl = g_delta[idx];
            float corr = 0.f;
#pragma unroll
            for (int s = 0; s < DSTATE; s++) {
                float la = fmaxf(dl * Areg[s], LNEPS);
                L[s] += la;
                corr = fmaf(h0r[s] * Cs[t * DSTATE + s], __expf(L[s]), corr);
            }
            y += corr;
        }
        const float zv = g_xz[(size_t)(m0 + t) * (2 * DINNER) + DINNER + d];
        const float sig = 1.f / (1.f + __expf(-zv));
        g_y[idx] = y * (zv * sig);
    }
}

// ---------------- launch ----------------
extern "C" void kernel_launch(void* const* d_in, const int* in_sizes, int n_in,
                              void* d_out, int out_size)
{
    const float* x       = (const float*)d_in[0];
    const float* in_w    = (const float*)d_in[1];
    const float* conv_w  = (const float*)d_in[2];
    const float* conv_b  = (const float*)d_in[3];
    const float* xpw     = (const float*)d_in[4];
    const float* dt_w    = (const float*)d_in[5];
    const float* dt_b    = (const float*)d_in[6];
    const float* A_log   = (const float*)d_in[7];
    const float* D_param = (const float*)d_in[8];
    const float* out_w   = (const float*)d_in[9];
    float* out           = (float*)d_out;

    float *p_xz, *p_y;
    __nv_bfloat16 *p_Xbig, *p_W1big, *p_Ybig, *p_W2big;
    cudaGetSymbolAddress((void**)&p_xz,    g_xz);
    cudaGetSymbolAddress((void**)&p_y,     g_y);
    cudaGetSymbolAddress((void**)&p_Xbig,  g_Xbig);
    cudaGetSymbolAddress((void**)&p_W1big, g_W1big);
    cudaGetSymbolAddress((void**)&p_Ybig,  g_Ybig);
    cudaGetSymbolAddress((void**)&p_W2big, g_W2big);

    // 0) pack x and in_proj_w into bf16 split triples
    pack3_kernel<<<(NTOK * DMODEL / 4) / 256, 256>>>(x, p_Xbig, DMODEL, 0);
    pack3_kernel<<<((2 * DINNER) * DMODEL / 4) / 256, 256>>>(in_w, p_W1big, DMODEL, 1);

    // 1) xz = x @ in_proj_w^T   (M=4096, N=4096, K'=3072)
    {
        dim3 grid((2 * DINNER) / 128, NTOK / 128);
        gemm_bf16_nt<<<grid, 256>>>(p_Xbig, p_W1big, p_xz, NTOK, 2 * DINNER, 3 * DMODEL);
    }
    // 2) conv + silu + x_proj + delta/B/C
    conv_proj_kernel<<<NTOK, 256>>>(conv_w, conv_b, xpw, dt_w, dt_b);
    // 3) per-chunk local scan
    {
        dim3 grid(DINNER / 256, NCHUNK, BATCH);
        scanA_kernel<<<grid, 256>>>(A_log, D_param);
    }
    // 4) chunk carry
    carry_kernel<<<(BATCH * DINNER * DSTATE) / 256, 256>>>();
    // 5) carry correction + gate
    {
        dim3 grid(DINNER / 256, NCHUNK, BATCH);
        scanB_kernel<<<grid, 256>>>(A_log);
    }
    // 6) pack y and out_proj_w, then out = y @ out_proj_w^T (M=4096,N=1024,K'=6144)
    pack3_kernel<<<(NTOK * DINNER / 4) / 256, 256>>>(p_y, p_Ybig, DINNER, 0);
    pack3_kernel<<<(DMODEL * DINNER / 4) / 256, 256>>>(out_w, p_W2big, DINNER, 1);
    {
        dim3 grid(DMODEL / 128, NTOK / 128);
        gemm_bf16_nt<<<grid, 256>>>(p_Ybig, p_W2big, out, NTOK, DMODEL, 3 * DINNER);
    }
}

// round 4
// speedup vs baseline: 1.8052x; 1.0883x over previous
#include <cuda_runtime.h>
#include <cuda_bf16.h>
#include <cstdint>

// ---------------- problem constants ----------------
#define BATCH    2
#define SEQLEN   2048
#define DMODEL   1024
#define DINNER   2048
#define DSTATE   16
#define DCONV    4
#define CHUNK    256
#define NCHUNK   (SEQLEN / CHUNK)          // 8
#define NTOK     (BATCH * SEQLEN)          // 4096
#define EPSF     1e-10f
#define LNEPS    (-23.025850929940457f)    // log(1e-10)

// ---------------- scratch (device globals: allocation-free) ----------------
__device__ float g_xz[NTOK * (2 * DINNER)];
__device__ float g_xc[NTOK * DINNER];
__device__ float g_delta[NTOK * DINNER];
__device__ float g_Bb[NTOK * DSTATE];
__device__ float g_Cc[NTOK * DSTATE];
__device__ float g_y[NTOK * DINNER];
__device__ float g_hloc[BATCH * NCHUNK * DINNER * DSTATE];
__device__ float g_Atot[BATCH * NCHUNK * DINNER * DSTATE];
__device__ float g_h0  [BATCH * NCHUNK * DINNER * DSTATE];

// bf16 split-GEMM operands: A' = [hi|lo|hi], B' = [hi|hi|lo] along K
__device__ __nv_bfloat16 g_Xbig [NTOK   * 3 * DMODEL];
__device__ __nv_bfloat16 g_W1big[(2*DINNER) * 3 * DMODEL];
__device__ __nv_bfloat16 g_Ybig [NTOK   * 3 * DINNER];
__device__ __nv_bfloat16 g_W2big[DMODEL * 3 * DINNER];

// ---------------- helpers ----------------
__device__ __forceinline__ uint32_t smem_u32(const void* p) {
    return (uint32_t)__cvta_generic_to_shared(p);
}
__device__ __forceinline__ void ldsm_x4(uint32_t& r0, uint32_t& r1,
                                        uint32_t& r2, uint32_t& r3, uint32_t addr) {
    asm volatile("ldmatrix.sync.aligned.m8n8.x4.shared.b16 {%0,%1,%2,%3}, [%4];"
                 : "=r"(r0), "=r"(r1), "=r"(r2), "=r"(r3) : "r"(addr));
}
__device__ __forceinline__ void mma_bf16(float* c, const uint32_t* a, const uint32_t* b) {
    asm volatile("mma.sync.aligned.m16n8k16.row.col.f32.bf16.bf16.f32 "
                 "{%0,%1,%2,%3}, {%4,%5,%6,%7}, {%8,%9}, {%0,%1,%2,%3};"
                 : "+f"(c[0]), "+f"(c[1]), "+f"(c[2]), "+f"(c[3])
                 : "r"(a[0]), "r"(a[1]), "r"(a[2]), "r"(a[3]), "r"(b[0]), "r"(b[1]));
}
__device__ __forceinline__ void cpasync16(uint32_t dst, const void* src) {
    asm volatile("cp.async.cg.shared.global [%0], [%1], 16;" :: "r"(dst), "l"(src));
}
__device__ __forceinline__ void cp_commit() {
    asm volatile("cp.async.commit_group;" ::: "memory");
}
template<int NWAIT>
__device__ __forceinline__ void cp_wait() {
    asm volatile("cp.async.wait_group %0;" :: "n"(NWAIT) : "memory");
}

// ---------------- bf16 tensor-core GEMM (mma.sync, 3-stage cp.async) -------
// C[M,N] = A[M,K] * B[N,K]^T. 128x128 tile, BK=32, 256 thr, warp tile 32x64.
#define BKP 40
#define GST_BYTES (128 * BKP * 2 * 2)     // A + B per stage = 20480
#define GSMEM_TOTAL (3 * GST_BYTES)       // 61440

__global__ __launch_bounds__(256, 2)
void gemm_mma(const __nv_bfloat16* __restrict__ A,
              const __nv_bfloat16* __restrict__ B,
              float* __restrict__ C, int N, int K)
{
    extern __shared__ char smem[];
    const int tid  = threadIdx.x;
    const int warp = tid >> 5, lane = tid & 31;
    const int wm = (warp & 3) << 5;
    const int wn = (warp >> 2) << 6;
    const size_t bM = (size_t)blockIdx.y * 128;
    const size_t bN = (size_t)blockIdx.x * 128;
    const int KT = K >> 5;

    float acc[2][8][4];
#pragma unroll
    for (int i = 0; i < 2; i++)
#pragma unroll
        for (int j = 0; j < 8; j++)
#pragma unroll
            for (int q = 0; q < 4; q++) acc[i][j][q] = 0.f;

    const int ldr  = tid >> 2;       // 0..63
    const int slot = tid & 3;        // 0..3 (8 bf16 each)

    auto load_stage = [&](int s, int k0) {
        char* sA = smem + s * GST_BYTES;
        char* sB = sA + 128 * BKP * 2;
        uint32_t da = smem_u32(sA) + (uint32_t)(ldr * BKP + slot * 8) * 2;
        uint32_t db = smem_u32(sB) + (uint32_t)(ldr * BKP + slot * 8) * 2;
        const __nv_bfloat16* ga = A + (bM + ldr) * (size_t)K + k0 + slot * 8;
        const __nv_bfloat16* gb = B + (bN + ldr) * (size_t)K + k0 + slot * 8;
        cpasync16(da, ga);
        cpasync16(da + 64 * BKP * 2, ga + 64 * (size_t)K);
        cpasync16(db, gb);
        cpasync16(db + 64 * BKP * 2, gb + 64 * (size_t)K);
    };

    load_stage(0, 0);  cp_commit();
    load_stage(1, 32); cp_commit();

    const int lrow  = lane & 15;
    const int lcolo = (lane >> 4) << 3;

    for (int kt = 0; kt < KT; kt++) {
        cp_wait<1>();
        __syncthreads();
        if (kt + 2 < KT) load_stage((kt + 2) % 3, (kt + 2) << 5);

        char* sS = smem + (kt % 3) * GST_BYTES;
        __nv_bfloat16 (*As)[BKP] = (__nv_bfloat16(*)[BKP])sS;
        __nv_bfloat16 (*Bs)[BKP] = (__nv_bfloat16(*)[BKP])(sS + 128 * BKP * 2);
#pragma unroll
        for (int kk = 0; kk < 32; kk += 16) {
            uint32_t af[2][4], bf[8][2];
#pragma unroll
            for (int i = 0; i < 2; i++)
                ldsm_x4(af[i][0], af[i][1], af[i][2], af[i][3],
                        smem_u32(&As[wm + i * 16 + lrow][kk + lcolo]));
#pragma unroll
            for (int j = 0; j < 4; j++) {
                uint32_t r0, r1, r2, r3;
                ldsm_x4(r0, r1, r2, r3,
                        smem_u32(&Bs[wn + j * 16 + lrow][kk + lcolo]));
                bf[2 * j][0] = r0; bf[2 * j + 1][0] = r1;
                bf[2 * j][1] = r2; bf[2 * j + 1][1] = r3;
            }
#pragma unroll
            for (int i = 0; i < 2; i++)
#pragma unroll
                for (int j = 0; j < 8; j++)
                    mma_bf16(acc[i][j], af[i], bf[j]);
        }
        cp_commit();
        __syncthreads();
    }

#pragma unroll
    for (int i = 0; i < 2; i++) {
        const size_t rbase = bM + wm + i * 16 + (lane >> 2);
#pragma unroll
        for (int j = 0; j < 8; j++) {
            const size_t col = bN + wn + j * 8 + (lane & 3) * 2;
            *(float2*)&C[rbase * N + col]       = make_float2(acc[i][j][0], acc[i][j][1]);
            *(float2*)&C[(rbase + 8) * N + col] = make_float2(acc[i][j][2], acc[i][j][3]);
        }
    }
}

// ---------------- fp32 -> bf16 hi/lo triple pack ----------------
__global__ __launch_bounds__(256)
void pack3_kernel(const float* __restrict__ src, __nv_bfloat16* __restrict__ dst,
                  int K, int mode)
{
    const int g = blockIdx.x * 256 + threadIdx.x;
    const int kq = K >> 2;
    const int r = g / kq;
    const int k4 = (g - r * kq) << 2;
    float4 v = *(const float4*)(src + (size_t)r * K + k4);
    float vv[4] = {v.x, v.y, v.z, v.w};
    __nv_bfloat16 h[4], l[4];
#pragma unroll
    for (int i = 0; i < 4; i++) {
        h[i] = __float2bfloat16(vv[i]);
        l[i] = __float2bfloat16(vv[i] - __bfloat162float(h[i]));
    }
    __nv_bfloat16* base = dst + (size_t)r * 3 * K;
    *(uint2*)&base[k4]           = *(uint2*)h;
    *(uint2*)&base[K + k4]       = mode ? *(uint2*)h : *(uint2*)l;
    *(uint2*)&base[2 * K + k4]   = mode ? *(uint2*)l : *(uint2*)h;
}

// ---------------- conv1d + silu + x_proj (token-batched) ----------------
// block = 8 tokens of one batch; grid (256, 2); 256 threads
#define CPT 8
#define XPPAD 257
#define CPSMEM ((CPT * DINNER + 33 * XPPAD + CPT * 33 + 8) * 4)

__global__ __launch_bounds__(256)
void conv_proj2(const float* __restrict__ conv_w,
                const float* __restrict__ conv_b,
                const float* __restrict__ xpw,    // (33, 2048)
                const float* __restrict__ dt_w,   // (2048,1)
                const float* __restrict__ dt_b)   // (2048,)
{
    extern __shared__ float sm[];
    float* sxc = sm;                        // CPT * 2048
    float* sxp = sm + CPT * DINNER;         // 33 * 257
    float* sps = sxp + 33 * XPPAD;          // CPT * 33

    const int b  = blockIdx.y;
    const int t0 = blockIdx.x * CPT;
    const int tid = threadIdx.x;
    const int warp = tid >> 5, lane = tid & 31;

    // phase 1: conv + silu for CPT tokens
#pragma unroll
    for (int k = 0; k < CPT * DINNER / 256; k++) {   // 64
        const int idx = tid + k * 256;
        const int tt = idx >> 11, d = idx & 2047;
        const int t = t0 + tt;
        float acc = conv_b[d];
#pragma unroll
        for (int kk = 0; kk < DCONV; kk++) {
            int ts = t - (DCONV - 1) + kk;
            float xv = (ts >= 0) ? g_xz[(size_t)(b * SEQLEN + ts) * (2 * DINNER) + d] : 0.f;
            acc = fmaf(conv_w[d * DCONV + kk], xv, acc);
        }
        float xcv = acc / (1.f + __expf(-acc));
        sxc[idx] = xcv;
        g_xc[(size_t)(b * SEQLEN + t) * DINNER + d] = xcv;
    }
    __syncthreads();

    // phase 2: xps[tt][j] = sum_d xc[tt][d] * xpw[j][d]; warp = token
    float accj = 0.f, acc32 = 0.f;
    for (int d0 = 0; d0 < DINNER; d0 += 256) {
#pragma unroll
        for (int m = 0; m < 33; m++) {               // 33*256 elems, 256 thr
            int e = tid + m * 256;
            int j = e >> 8, i = e & 255;
            sxp[j * XPPAD + i] = xpw[j * DINNER + d0 + i];
        }
        __syncthreads();
        const float* xr = &sxc[warp * DINNER + d0];
#pragma unroll 8
        for (int dd = 0; dd < 256; dd++)
            accj = fmaf(xr[dd], sxp[lane * XPPAD + dd], accj);
        // j = 32 handled lane-parallel
#pragma unroll
        for (int dd = lane; dd < 256; dd += 32)
            acc32 = fmaf(xr[dd], sxp[32 * XPPAD + dd], acc32);
        __syncthreads();
    }
#pragma unroll
    for (int off = 16; off > 0; off >>= 1)
        acc32 += __shfl_down_sync(0xffffffffu, acc32, off);
    sps[warp * 33 + lane] = accj;
    if (lane == 0) sps[warp * 33 + 32] = acc32;
    __syncthreads();

    // phase 3: delta (softplus) + B/C extraction
#pragma unroll
    for (int k = 0; k < CPT * DINNER / 256; k++) {
        const int idx = tid + k * 256;
        const int tt = idx >> 11, d = idx & 2047;
        float u = fmaf(sps[tt * 33], dt_w[d], dt_b[d]);
        float sp = fmaxf(u, 0.f) + log1pf(__expf(-fabsf(u)));
        g_delta[(size_t)(b * SEQLEN + t0 + tt) * DINNER + d] = sp;
    }
    if (tid < CPT * DSTATE) {
        const int tt = tid >> 4, s = tid & 15;
        const int m = b * SEQLEN + t0 + tt;
        g_Bb[m * DSTATE + s] = sps[tt * 33 + 1 + s];
        g_Cc[m * DSTATE + s] = sps[tt * 33 + 1 + DSTATE + s];
    }
}

// ---------------- scan pass A: per-chunk local recurrence (h0 = 0) ----------
__global__ __launch_bounds__(256)
void scanA_kernel(const float* __restrict__ A_log,
                  const float* __restrict__ D_param)
{
    const int d = blockIdx.x * 256 + threadIdx.x;
    const int c = blockIdx.y;
    const int b = blockIdx.z;
    const int m0 = b * SEQLEN + c * CHUNK;

    __shared__ float Bs[CHUNK * DSTATE];
    __shared__ float Cs[CHUNK * DSTATE];
    {
        const float4* gb = (const float4*)(g_Bb + (size_t)m0 * DSTATE);
        const float4* gc = (const float4*)(g_Cc + (size_t)m0 * DSTATE);
        for (int i = threadIdx.x; i < CHUNK * DSTATE / 4; i += 256) {
            ((float4*)Bs)[i] = gb[i];
            ((float4*)Cs)[i] = gc[i];
        }
    }

    float Areg[DSTATE];
#pragma unroll
    for (int s = 0; s < DSTATE; s++) Areg[s] = -expf(A_log[s]);
    const float Dd = D_param[d];
    __syncthreads();

    float L[DSTATE], W[DSTATE], E[DSTATE], H[DSTATE];
#pragma unroll
    for (int s = 0; s < DSTATE; s++) { L[s] = 0.f; W[s] = 0.f; E[s] = 1.f; H[s] = 0.f; }

    for (int t = 0; t < CHUNK; t++) {
        const size_t idx = (size_t)(m0 + t) * DINNER + d;
        const float dl  = g_delta[idx];
        const float xcv = g_xc[idx];
        const float dx  = dl * xcv;
        float y = Dd * xcv;
#pragma unroll
        for (int s = 0; s < DSTATE; s++) {
            float la = fmaxf(dl * Areg[s], LNEPS);
            L[s] += la;
            float en = __expf(L[s]);
            float bx = dx * Bs[t * DSTATE + s];
            W[s] += __fdividef(bx, fmaxf(E[s], EPSF));
            float h = E[s] * W[s];
            H[s] = h;
            y = fmaf(Cs[t * DSTATE + s], h, y);
            E[s] = en;
        }
        g_y[idx] = y;
    }
    const size_t o = ((size_t)(b * NCHUNK + c) * DINNER + d) * DSTATE;
#pragma unroll
    for (int s = 0; s < DSTATE; s++) {
        g_hloc[o + s] = H[s];
        g_Atot[o + s] = E[s];
    }
}

// ---------------- chunk carry ----------------
__global__ __launch_bounds__(256)
void carry_kernel()
{
    const int i = blockIdx.x * 256 + threadIdx.x;
    const int s = i & (DSTATE - 1);
    const int d = (i >> 4) & (DINNER - 1);
    const int b = i >> 15;
    float h = 0.f;
#pragma unroll
    for (int c = 0; c < NCHUNK; c++) {
        const size_t o = ((size_t)(b * NCHUNK + c) * DINNER + d) * DSTATE + s;
        g_h0[o] = h;
        h = g_hloc[o] + h * g_Atot[o];
    }
}

// ---------------- scan pass B: + C·h0·A_cum, then silu(z) gate --------------
__global__ __launch_bounds__(256)
void scanB_kernel(const float* __restrict__ A_log)
{
    const int d = blockIdx.x * 256 + threadIdx.x;
    const int c = blockIdx.y;
    const int b = blockIdx.z;
    const int m0 = b * SEQLEN + c * CHUNK;

    __shared__ float Cs[CHUNK * DSTATE];
    {
        const float4* gc = (const float4*)(g_Cc + (size_t)m0 * DSTATE);
        for (int i = threadIdx.x; i < CHUNK * DSTATE / 4; i += 256)
            ((float4*)Cs)[i] = gc[i];
    }

    float Areg[DSTATE], h0r[DSTATE], L[DSTATE];
    const size_t o = ((size_t)(b * NCHUNK + c) * DINNER + d) * DSTATE;
    bool any = false;
#pragma unroll
    for (int s = 0; s < DSTATE; s++) {
        Areg[s] = -expf(A_log[s]);
        h0r[s] = g_h0[o + s];
        L[s] = 0.f;
        any = any || (h0r[s] != 0.f);
    }
    __syncthreads();

    for (int t = 0; t < CHUNK; t++) {
        const size_t idx = (size_t)(m0 + t) * DINNER + d;
        float y = g_y[idx];
        if (any) {
            const float dl = g_delta[idx];
            float corr = 0.f;
#pragma unroll
            for (int s = 0; s < DSTATE; s++) {
                float la = fmaxf(dl * Areg[s], LNEPS);
                L[s] += la;
                corr = fmaf(h0r[s] * Cs[t * DSTATE + s], __expf(L[s]), corr);
            }
            y += corr;
        }
        const float zv = g_xz[(size_t)(m0 + t) * (2 * DINNER) + DINNER + d];
        const float sig = 1.f / (1.f + __expf(-zv));
        g_y[idx] = y * (zv * sig);
    }
}

// ---------------- launch ----------------
extern "C" void kernel_launch(void* const* d_in, const int* in_sizes, int n_in,
                              void* d_out, int out_size)
{
    const float* x       = (const float*)d_in[0];
    const float* in_w    = (const float*)d_in[1];
    const float* conv_w  = (const float*)d_in[2];
    const float* conv_b  = (const float*)d_in[3];
    const float* xpw     = (const float*)d_in[4];
    const float* dt_w    = (const float*)d_in[5];
    const float* dt_b    = (const float*)d_in[6];
    const float* A_log   = (const float*)d_in[7];
    const float* D_param = (const float*)d_in[8];
    const float* out_w   = (const float*)d_in[9];
    float* out           = (float*)d_out;

    float *p_xz, *p_y;
    __nv_bfloat16 *p_Xbig, *p_W1big, *p_Ybig, *p_W2big;
    cudaGetSymbolAddress((void**)&p_xz,    g_xz);
    cudaGetSymbolAddress((void**)&p_y,     g_y);
    cudaGetSymbolAddress((void**)&p_Xbig,  g_Xbig);
    cudaGetSymbolAddress((void**)&p_W1big, g_W1big);
    cudaGetSymbolAddress((void**)&p_Ybig,  g_Ybig);
    cudaGetSymbolAddress((void**)&p_W2big, g_W2big);

    cudaFuncSetAttribute(gemm_mma, cudaFuncAttributeMaxDynamicSharedMemorySize,
                         GSMEM_TOTAL);
    cudaFuncSetAttribute(conv_proj2, cudaFuncAttributeMaxDynamicSharedMemorySize,
                         CPSMEM);

    // 0) pack x and in_proj_w into bf16 split triples
    pack3_kernel<<<(NTOK * DMODEL / 4) / 256, 256>>>(x, p_Xbig, DMODEL, 0);
    pack3_kernel<<<((2 * DINNER) * DMODEL / 4) / 256, 256>>>(in_w, p_W1big, DMODEL, 1);

    // 1) xz = x @ in_proj_w^T   (M=4096, N=4096, K'=3072)
    {
        dim3 grid((2 * DINNER) / 128, NTOK / 128);
        gemm_mma<<<grid, 256, GSMEM_TOTAL>>>(p_Xbig, p_W1big, p_xz, 2 * DINNER, 3 * DMODEL);
    }
    // 2) conv + silu + x_proj + delta/B/C (token-batched)
    {
        dim3 grid(SEQLEN / CPT, BATCH);
        conv_proj2<<<grid, 256, CPSMEM>>>(conv_w, conv_b, xpw, dt_w, dt_b);
    }
    // 3) per-chunk local scan
    {
        dim3 grid(DINNER / 256, NCHUNK, BATCH);
        scanA_kernel<<<grid, 256>>>(A_log, D_param);
    }
    // 4) chunk carry
    carry_kernel<<<(BATCH * DINNER * DSTATE) / 256, 256>>>();
    // 5) carry correction + gate
    {
        dim3 grid(DINNER / 256, NCHUNK, BATCH);
        scanB_kernel<<<grid, 256>>>(A_log);
    }
    // 6) pack y and out_proj_w, then out = y @ out_proj_w^T (M=4096,N=1024,K'=6144)
    pack3_kernel<<<(NTOK * DINNER / 4) / 256, 256>>>(p_y, p_Ybig, DINNER, 0);
    pack3_kernel<<<(DMODEL * DINNER / 4) / 256, 256>>>(out_w, p_W2big, DINNER, 1);
    {
        dim3 grid(DMODEL / 128, NTOK / 128);
        gemm_mma<<<grid, 256, GSMEM_TOTAL>>>(p_Ybig, p_W2big, out, DMODEL, 3 * DINNER);
    }
}

// round 5
// speedup vs baseline: 1.9146x; 1.0606x over previous
#include <cuda_runtime.h>
#include <cuda_bf16.h>
#include <cstdint>

// ---------------- problem constants ----------------
#define BATCH    2
#define SEQLEN   2048
#define DMODEL   1024
#define DINNER   2048
#define DSTATE   16
#define DCONV    4
#define CHUNK    256
#define NCHUNK   (SEQLEN / CHUNK)          // 8
#define NTOK     (BATCH * SEQLEN)          // 4096
#define EPSF     1e-10f
#define LNEPS    (-23.025850929940457f)    // log(1e-10)
#define LDEAD    (-60.0f)
#define HTHRESH  1e-13f

// ---------------- scratch (device globals: allocation-free) ----------------
__device__ float g_xz[NTOK * (2 * DINNER)];
__device__ float g_xc[NTOK * DINNER];
__device__ float g_delta[NTOK * DINNER];
__device__ float g_Bb[NTOK * DSTATE];
__device__ float g_Cc[NTOK * DSTATE];
__device__ float g_y[NTOK * DINNER];
__device__ float g_hloc[BATCH * NCHUNK * DINNER * DSTATE];
__device__ float g_Atot[BATCH * NCHUNK * DINNER * DSTATE];
__device__ float g_h0  [BATCH * NCHUNK * DINNER * DSTATE];

// bf16 split-GEMM operands, stored [hi | lo] along K (row stride 2K)
__device__ __nv_bfloat16 g_Xbig [NTOK * 2 * DMODEL];
__device__ __nv_bfloat16 g_W1big[(2 * DINNER) * 2 * DMODEL];
__device__ __nv_bfloat16 g_Ybig [NTOK * 2 * DINNER];
__device__ __nv_bfloat16 g_W2big[DMODEL * 2 * DINNER];

// ---------------- helpers ----------------
__device__ __forceinline__ uint32_t smem_u32(const void* p) {
    return (uint32_t)__cvta_generic_to_shared(p);
}
__device__ __forceinline__ void ldsm_x4(uint32_t& r0, uint32_t& r1,
                                        uint32_t& r2, uint32_t& r3, uint32_t addr) {
    asm volatile("ldmatrix.sync.aligned.m8n8.x4.shared.b16 {%0,%1,%2,%3}, [%4];"
                 : "=r"(r0), "=r"(r1), "=r"(r2), "=r"(r3) : "r"(addr));
}
__device__ __forceinline__ void mma_bf16(float* c, const uint32_t* a, const uint32_t* b) {
    asm volatile("mma.sync.aligned.m16n8k16.row.col.f32.bf16.bf16.f32 "
                 "{%0,%1,%2,%3}, {%4,%5,%6,%7}, {%8,%9}, {%0,%1,%2,%3};"
                 : "+f"(c[0]), "+f"(c[1]), "+f"(c[2]), "+f"(c[3])
                 : "r"(a[0]), "r"(a[1]), "r"(a[2]), "r"(a[3]), "r"(b[0]), "r"(b[1]));
}
__device__ __forceinline__ void cpasync16(uint32_t dst, const void* src) {
    asm volatile("cp.async.cg.shared.global [%0], [%1], 16;" :: "r"(dst), "l"(src));
}
__device__ __forceinline__ void cp_commit() {
    asm volatile("cp.async.commit_group;" ::: "memory");
}
template<int NWAIT>
__device__ __forceinline__ void cp_wait() {
    asm volatile("cp.async.wait_group %0;" :: "n"(NWAIT) : "memory");
}
__device__ __forceinline__ int warp_max(int v) {
#pragma unroll
    for (int off = 16; off > 0; off >>= 1)
        v = max(v, __shfl_xor_sync(0xffffffffu, v, off));
    return v;
}

// ---------------- bf16 tensor-core GEMM (mma.sync, 4-stage cp.async) -------
// C[M,N] = A'[M,3K] * B'[N,3K]^T with A' = [ah|al|ah], B' = [bh|bh|bl],
// A,B stored as [hi|lo] (row stride 2K); phase offsets recreate the triple.
#define BKP 40
#define GST_BYTES (128 * BKP * 2 * 2)     // 20480
#define GSMEM_TOTAL (4 * GST_BYTES)       // 81920

__global__ __launch_bounds__(256, 2)
void gemm_mma(const __nv_bfloat16* __restrict__ A,
              const __nv_bfloat16* __restrict__ B,
              float* __restrict__ C, int N, int K1)
{
    extern __shared__ char smem[];
    const int tid  = threadIdx.x;
    const int warp = tid >> 5, lane = tid & 31;
    const int wm = (warp & 3) << 5;
    const int wn = (warp >> 2) << 6;
    const size_t bM = (size_t)blockIdx.y * 128;
    const size_t bN = (size_t)blockIdx.x * 128;
    const int kt1 = K1 >> 5;
    const int KT  = 3 * kt1;
    const size_t lda = 2 * (size_t)K1;

    float acc[2][8][4];
#pragma unroll
    for (int i = 0; i < 2; i++)
#pragma unroll
        for (int j = 0; j < 8; j++)
#pragma unroll
            for (int q = 0; q < 4; q++) acc[i][j][q] = 0.f;

    const int ldr  = tid >> 2;       // 0..63
    const int slot = tid & 3;        // 0..3 (8 bf16 each)

    auto load_stage = [&](int s, int ktAbs) {
        int ph = (ktAbs >= 2 * kt1) ? 2 : ((ktAbs >= kt1) ? 1 : 0);
        int kk = (ktAbs - ph * kt1) << 5;
        int offA = (ph == 1) ? K1 : 0;
        int offB = (ph == 2) ? K1 : 0;
        char* sA = smem + s * GST_BYTES;
        char* sB = sA + 128 * BKP * 2;
        uint32_t da = smem_u32(sA) + (uint32_t)(ldr * BKP + slot * 8) * 2;
        uint32_t db = smem_u32(sB) + (uint32_t)(ldr * BKP + slot * 8) * 2;
        const __nv_bfloat16* ga = A + (bM + ldr) * lda + offA + kk + slot * 8;
        const __nv_bfloat16* gb = B + (bN + ldr) * lda + offB + kk + slot * 8;
        cpasync16(da, ga);
        cpasync16(da + 64 * BKP * 2, ga + 64 * lda);
        cpasync16(db, gb);
        cpasync16(db + 64 * BKP * 2, gb + 64 * lda);
    };

    load_stage(0, 0); cp_commit();
    load_stage(1, 1); cp_commit();
    load_stage(2, 2); cp_commit();

    const int lrow  = lane & 15;
    const int lcolo = (lane >> 4) << 3;

    for (int kt = 0; kt < KT; kt++) {
        cp_wait<2>();
        __syncthreads();
        if (kt + 3 < KT) load_stage((kt + 3) & 3, kt + 3);
        cp_commit();

        char* sS = smem + (kt & 3) * GST_BYTES;
        __nv_bfloat16 (*As)[BKP] = (__nv_bfloat16(*)[BKP])sS;
        __nv_bfloat16 (*Bs)[BKP] = (__nv_bfloat16(*)[BKP])(sS + 128 * BKP * 2);
#pragma unroll
        for (int kk = 0; kk < 32; kk += 16) {
            uint32_t af[2][4], bf[8][2];
#pragma unroll
            for (int i = 0; i < 2; i++)
                ldsm_x4(af[i][0], af[i][1], af[i][2], af[i][3],
                        smem_u32(&As[wm + i * 16 + lrow][kk + lcolo]));
#pragma unroll
            for (int j = 0; j < 4; j++) {
                uint32_t r0, r1, r2, r3;
                ldsm_x4(r0, r1, r2, r3,
                        smem_u32(&Bs[wn + j * 16 + lrow][kk + lcolo]));
                bf[2 * j][0] = r0; bf[2 * j + 1][0] = r1;
                bf[2 * j][1] = r2; bf[2 * j + 1][1] = r3;
            }
#pragma unroll
            for (int i = 0; i < 2; i++)
#pragma unroll
                for (int j = 0; j < 8; j++)
                    mma_bf16(acc[i][j], af[i], bf[j]);
        }
    }

#pragma unroll
    for (int i = 0; i < 2; i++) {
        const size_t rbase = bM + wm + i * 16 + (lane >> 2);
#pragma unroll
        for (int j = 0; j < 8; j++) {
            const size_t col = bN + wn + j * 8 + (lane & 3) * 2;
            *(float2*)&C[rbase * N + col]       = make_float2(acc[i][j][0], acc[i][j][1]);
            *(float2*)&C[(rbase + 8) * N + col] = make_float2(acc[i][j][2], acc[i][j][3]);
        }
    }
}

// ---------------- fp32 -> bf16 [hi|lo] pack ----------------
__global__ __launch_bounds__(256)
void pack2_kernel(const float* __restrict__ src, __nv_bfloat16* __restrict__ dst,
                  int K)
{
    const int g = blockIdx.x * 256 + threadIdx.x;
    const int kq = K >> 2;
    const int r = g / kq;
    const int k4 = (g - r * kq) << 2;
    float4 v = *(const float4*)(src + (size_t)r * K + k4);
    float vv[4] = {v.x, v.y, v.z, v.w};
    __nv_bfloat16 h[4], l[4];
#pragma unroll
    for (int i = 0; i < 4; i++) {
        h[i] = __float2bfloat16(vv[i]);
        l[i] = __float2bfloat16(vv[i] - __bfloat162float(h[i]));
    }
    __nv_bfloat16* base = dst + (size_t)r * 2 * K;
    *(uint2*)&base[k4]     = *(uint2*)h;
    *(uint2*)&base[K + k4] = *(uint2*)l;
}

// ---------------- y gating + bf16 [hi|lo] pack (fused) ----------------
__global__ __launch_bounds__(256)
void pack2y_kernel()
{
    const int g = blockIdx.x * 256 + threadIdx.x;        // NTOK*DINNER/4
    const int m  = g >> 9;                               // DINNER/4 = 512
    const int k4 = (g & 511) << 2;
    float4 yv = *(const float4*)(g_y + (size_t)m * DINNER + k4);
    float4 zv = *(const float4*)(g_xz + (size_t)m * (2 * DINNER) + DINNER + k4);
    float yy[4] = {yv.x, yv.y, yv.z, yv.w};
    float zz[4] = {zv.x, zv.y, zv.z, zv.w};
    __nv_bfloat16 h[4], l[4];
#pragma unroll
    for (int i = 0; i < 4; i++) {
        float sig = 1.f / (1.f + __expf(-zz[i]));
        float gv = yy[i] * zz[i] * sig;
        h[i] = __float2bfloat16(gv);
        l[i] = __float2bfloat16(gv - __bfloat162float(h[i]));
    }
    __nv_bfloat16* base = g_Ybig + (size_t)m * 2 * DINNER;
    *(uint2*)&base[k4]          = *(uint2*)h;
    *(uint2*)&base[DINNER + k4] = *(uint2*)l;
}

// ---------------- conv1d + silu + x_proj (token-batched v3) ----------------
#define CT   16
#define DC   256
#define SXPP 260
#define CPSMEM ((CT * DC + 33 * SXPP + CT * 33) * 4)   // 52816 B

__global__ __launch_bounds__(256)
void conv_proj3(const float* __restrict__ conv_w,
                const float* __restrict__ conv_b,
                const float* __restrict__ xpw,    // (33, 2048)
                const float* __restrict__ dt_w,   // (2048,1)
                const float* __restrict__ dt_b)   // (2048,)
{
    extern __shared__ float sm[];
    float* sxc = sm;                    // [CT][DC]
    float* sxp = sm + CT * DC;          // [33][SXPP]
    float* sps = sxp + 33 * SXPP;       // [CT][33]

    const int b  = blockIdx.y;
    const int t0 = blockIdx.x * CT;
    const int tid = threadIdx.x;
    const int warp = tid >> 5, lane = tid & 31;

    float acc[2]   = {0.f, 0.f};        // j = lane, tokens warp*2 + {0,1}
    float acc32[2] = {0.f, 0.f};        // j = 32

    for (int d0 = 0; d0 < DINNER; d0 += DC) {
        // phase A: conv + silu into smem (and g_xc)
#pragma unroll
        for (int k = 0; k < CT * DC / 256; k++) {
            const int idx = tid + (k << 8);
            const int tt = idx >> 8, dd = idx & 255;
            const int t = t0 + tt, d = d0 + dd;
            float cv = conv_b[d];
#pragma unroll
            for (int kk = 0; kk < DCONV; kk++) {
                int ts = t - (DCONV - 1) + kk;
                float xv = (ts >= 0) ? g_xz[(size_t)(b * SEQLEN + ts) * (2 * DINNER) + d] : 0.f;
                cv = fmaf(conv_w[d * DCONV + kk], xv, cv);
            }
            float xcv = cv / (1.f + __expf(-cv));
            sxc[tt * DC + dd] = xcv;
            g_xc[(size_t)(b * SEQLEN + t) * DINNER + d] = xcv;
        }
        // load xpw chunk
#pragma unroll
        for (int m = 0; m < 33; m++)
            sxp[m * SXPP + tid] = xpw[m * DINNER + d0 + tid];
        __syncthreads();

        // phase B: per-warp 2 tokens x 32 lanes(j)
        const float* xr0 = sxc + (warp * 2 + 0) * DC;
        const float* xr1 = sxc + (warp * 2 + 1) * DC;
        const float* wvp = sxp + lane * SXPP;
#pragma unroll 8
        for (int dd0 = 0; dd0 < DC; dd0 += 4) {
            float4 w4 = *(const float4*)(wvp + dd0);
            float4 x0 = *(const float4*)(xr0 + dd0);
            float4 x1 = *(const float4*)(xr1 + dd0);
            acc[0] = fmaf(x0.x, w4.x, acc[0]); acc[0] = fmaf(x0.y, w4.y, acc[0]);
            acc[0] = fmaf(x0.z, w4.z, acc[0]); acc[0] = fmaf(x0.w, w4.w, acc[0]);
            acc[1] = fmaf(x1.x, w4.x, acc[1]); acc[1] = fmaf(x1.y, w4.y, acc[1]);
            acc[1] = fmaf(x1.z, w4.z, acc[1]); acc[1] = fmaf(x1.w, w4.w, acc[1]);
        }
        const float* w32 = sxp + 32 * SXPP;
#pragma unroll
        for (int dd = lane; dd < DC; dd += 32) {
            float wvv = w32[dd];
            acc32[0] = fmaf(xr0[dd], wvv, acc32[0]);
            acc32[1] = fmaf(xr1[dd], wvv, acc32[1]);
        }
        __syncthreads();
    }
    // reduce acc32 across lanes
#pragma unroll
    for (int tk = 0; tk < 2; tk++) {
#pragma unroll
        for (int off = 16; off > 0; off >>= 1)
            acc32[tk] += __shfl_down_sync(0xffffffffu, acc32[tk], off);
    }
#pragma unroll
    for (int tk = 0; tk < 2; tk++) {
        sps[(warp * 2 + tk) * 33 + lane] = acc[tk];
        if (lane == 0) sps[(warp * 2 + tk) * 33 + 32] = acc32[tk];
    }
    __syncthreads();

    // phase C: delta (softplus)
    for (int k = 0; k < CT * DINNER / 256; k++) {
        const int idx = tid + k * 256;
        const int tt = idx >> 11, d = idx & 2047;
        float u = fmaf(sps[tt * 33], dt_w[d], dt_b[d]);
        float sp = fmaxf(u, 0.f) + log1pf(__expf(-fabsf(u)));
        g_delta[(size_t)(b * SEQLEN + t0 + tt) * DINNER + d] = sp;
    }
    // B/C extraction: CT*16 = 256 entries
    {
        const int tt = tid >> 4, s = tid & 15;
        const int m = b * SEQLEN + t0 + tt;
        g_Bb[m * DSTATE + s] = sps[tt * 33 + 1 + s];
        g_Cc[m * DSTATE + s] = sps[tt * 33 + 1 + DSTATE + s];
    }
}

// ---------------- scan pass A: per-chunk local recurrence, dead-state skip --
__global__ __launch_bounds__(256)
void scanA_kernel(const float* __restrict__ A_log,
                  const float* __restrict__ D_param)
{
    const int d = blockIdx.x * 256 + threadIdx.x;
    const int c = blockIdx.y;
    const int b = blockIdx.z;
    const int m0 = b * SEQLEN + c * CHUNK;

    __shared__ float Bs[CHUNK * DSTATE];
    __shared__ float Cs[CHUNK * DSTATE];
    {
        const float4* gb = (const float4*)(g_Bb + (size_t)m0 * DSTATE);
        const float4* gc = (const float4*)(g_Cc + (size_t)m0 * DSTATE);
        for (int i = threadIdx.x; i < CHUNK * DSTATE / 4; i += 256) {
            ((float4*)Bs)[i] = gb[i];
            ((float4*)Cs)[i] = gc[i];
        }
    }

    float Areg[DSTATE];
#pragma unroll
    for (int s = 0; s < DSTATE; s++) Areg[s] = -expf(A_log[s]);
    const float Dd = D_param[d];
    __syncthreads();

    float L[DSTATE], W[DSTATE], H[DSTATE];
#pragma unroll
    for (int s = 0; s < DSTATE; s++) { L[s] = 0.f; W[s] = 0.f; H[s] = 0.f; }

    int nalive = DSTATE;
    for (int t = 0; t < CHUNK; t++) {
        const size_t idx = (size_t)(m0 + t) * DINNER + d;
        const float dl  = g_delta[idx];
        const float xcv = g_xc[idx];
        const float dx  = dl * xcv;
        float y = Dd * xcv;
        int cnt = 0;
#pragma unroll
        for (int s = 0; s < DSTATE; s++) {
            if (s < nalive) {
                float e = __expf(L[s]);                   // A_cum_sh
                float bx = dx * Bs[t * DSTATE + s];
                W[s] += __fdividef(bx, fmaxf(e, EPSF));
                float h = e * W[s];
                H[s] = h;
                y = fmaf(Cs[t * DSTATE + s], h, y);
                L[s] += fmaxf(dl * Areg[s], LNEPS);
                if (L[s] > LDEAD) cnt = s + 1;
            }
        }
        g_y[idx] = y;
        nalive = warp_max(cnt);
    }
    const size_t o = ((size_t)(b * NCHUNK + c) * DINNER + d) * DSTATE;
#pragma unroll
    for (int s = 0; s < DSTATE; s++) {
        g_hloc[o + s] = H[s];
        g_Atot[o + s] = __expf(L[s]);
    }
}

// ---------------- chunk carry ----------------
__global__ __launch_bounds__(256)
void carry_kernel()
{
    const int i = blockIdx.x * 256 + threadIdx.x;
    const int s = i & (DSTATE - 1);
    const int d = (i >> 4) & (DINNER - 1);
    const int b = i >> 15;
    float h = 0.f;
#pragma unroll
    for (int c = 0; c < NCHUNK; c++) {
        const size_t o = ((size_t)(b * NCHUNK + c) * DINNER + d) * DSTATE + s;
        g_h0[o] = h;
        h = g_hloc[o] + h * g_Atot[o];
    }
}

// ---------------- scan pass B: y += C·h0·A_cum (no gating here) ------------
__global__ __launch_bounds__(256)
void scanB_kernel(const float* __restrict__ A_log)
{
    const int d = blockIdx.x * 256 + threadIdx.x;
    const int c = blockIdx.y;
    const int b = blockIdx.z;
    const int m0 = b * SEQLEN + c * CHUNK;

    __shared__ float Cs[CHUNK * DSTATE];
    {
        const float4* gc = (const float4*)(g_Cc + (size_t)m0 * DSTATE);
        for (int i = threadIdx.x; i < CHUNK * DSTATE / 4; i += 256)
            ((float4*)Cs)[i] = gc[i];
    }

    float Areg[DSTATE], h0r[DSTATE], L[DSTATE];
    const size_t o = ((size_t)(b * NCHUNK + c) * DINNER + d) * DSTATE;
    int cnt = 0;
#pragma unroll
    for (int s = 0; s < DSTATE; s++) {
        Areg[s] = -expf(A_log[s]);
        h0r[s] = g_h0[o + s];
        L[s] = 0.f;
        if (fabsf(h0r[s]) > HTHRESH) cnt = s + 1;
    }
    __syncthreads();
    int nalive = warp_max(cnt);

    for (int t = 0; t < CHUNK && nalive > 0; t++) {
        const size_t idx = (size_t)(m0 + t) * DINNER + d;
        const float dl = g_delta[idx];
        float corr = 0.f;
        int c2 = 0;
#pragma unroll
        for (int s = 0; s < DSTATE; s++) {
            if (s < nalive) {
                L[s] += fmaxf(dl * Areg[s], LNEPS);
                corr = fmaf(h0r[s] * Cs[t * DSTATE + s], __expf(L[s]), corr);
                if (L[s] > LDEAD && fabsf(h0r[s]) > HTHRESH) c2 = s + 1;
            }
        }
        g_y[idx] += corr;
        nalive = warp_max(c2);
    }
}

// ---------------- launch ----------------
extern "C" void kernel_launch(void* const* d_in, const int* in_sizes, int n_in,
                              void* d_out, int out_size)
{
    const float* x       = (const float*)d_in[0];
    const float* in_w    = (const float*)d_in[1];
    const float* conv_w  = (const float*)d_in[2];
    const float* conv_b  = (const float*)d_in[3];
    const float* xpw     = (const float*)d_in[4];
    const float* dt_w    = (const float*)d_in[5];
    const float* dt_b    = (const float*)d_in[6];
    const float* A_log   = (const float*)d_in[7];
    const float* D_param = (const float*)d_in[8];
    const float* out_w   = (const float*)d_in[9];
    float* out           = (float*)d_out;

    float *p_xz;
    __nv_bfloat16 *p_Xbig, *p_W1big, *p_Ybig, *p_W2big;
    cudaGetSymbolAddress((void**)&p_xz,    g_xz);
    cudaGetSymbolAddress((void**)&p_Xbig,  g_Xbig);
    cudaGetSymbolAddress((void**)&p_W1big, g_W1big);
    cudaGetSymbolAddress((void**)&p_Ybig,  g_Ybig);
    cudaGetSymbolAddress((void**)&p_W2big, g_W2big);

    cudaFuncSetAttribute(gemm_mma, cudaFuncAttributeMaxDynamicSharedMemorySize,
                         GSMEM_TOTAL);
    cudaFuncSetAttribute(conv_proj3, cudaFuncAttributeMaxDynamicSharedMemorySize,
                         CPSMEM);

    // 0) pack x and in_proj_w into [hi|lo]
    pack2_kernel<<<(NTOK * DMODEL / 4) / 256, 256>>>(x, p_Xbig, DMODEL);
    pack2_kernel<<<((2 * DINNER) * DMODEL / 4) / 256, 256>>>(in_w, p_W1big, DMODEL);

    // 1) xz = x @ in_proj_w^T  (M=4096, N=4096, K1=1024 -> 3 phases)
    {
        dim3 grid((2 * DINNER) / 128, NTOK / 128);
        gemm_mma<<<grid, 256, GSMEM_TOTAL>>>(p_Xbig, p_W1big, p_xz, 2 * DINNER, DMODEL);
    }
    // 2) conv + silu + x_proj + delta/B/C
    {
        dim3 grid(SEQLEN / CT, BATCH);
        conv_proj3<<<grid, 256, CPSMEM>>>(conv_w, conv_b, xpw, dt_w, dt_b);
    }
    // 3) per-chunk local scan (dead-state skipping)
    {
        dim3 grid(DINNER / 256, NCHUNK, BATCH);
        scanA_kernel<<<grid, 256>>>(A_log, D_param);
    }
    // 4) chunk carry
    carry_kernel<<<(BATCH * DINNER * DSTATE) / 256, 256>>>();
    // 5) carry correction (sparse)
    {
        dim3 grid(DINNER / 256, NCHUNK, BATCH);
        scanB_kernel<<<grid, 256>>>(A_log);
    }
    // 6) gate + pack y, pack out_proj_w, then out = y @ out_proj_w^T
    pack2y_kernel<<<(NTOK * DINNER / 4) / 256, 256>>>();
    pack2_kernel<<<(DMODEL * DINNER / 4) / 256, 256>>>(out_w, p_W2big, DINNER);
    {
        dim3 grid(DMODEL / 128, NTOK / 128);
        gemm_mma<<<grid, 256, GSMEM_TOTAL>>>(p_Ybig, p_W2big, out, DMODEL, DINNER);
    }
}

// round 6
// speedup vs baseline: 2.0724x; 1.0824x over previous
#include <cuda_runtime.h>
#include <cuda_bf16.h>
#include <cstdint>

// ---------------- problem constants ----------------
#define BATCH    2
#define SEQLEN   2048
#define DMODEL   1024
#define DINNER   2048
#define DSTATE   16
#define DCONV    4
#define CHUNK    256
#define NCHUNK   (SEQLEN / CHUNK)          // 8
#define NTOK     (BATCH * SEQLEN)          // 4096
#define EPSF     1e-10f
#define LNEPS    (-23.025850929940457f)    // log(1e-10)
#define LDEAD    (-60.0f)
#define HTHRESH  1e-13f

// ---------------- scratch (device globals: allocation-free) ----------------
__device__ float g_xz[NTOK * (2 * DINNER)];
__device__ float g_y[NTOK * DINNER];
__device__ float g_xp0[NTOK];
__device__ float g_xpp[2 * NTOK * 33];       // D-split partial x_proj sums
__device__ float g_Bb[NTOK * DSTATE];
__device__ float g_Cc[NTOK * DSTATE];
__device__ float g_hloc[BATCH * NCHUNK * DINNER * DSTATE];
__device__ float g_Atot[BATCH * NCHUNK * DINNER * DSTATE];
__device__ float g_h0  [BATCH * NCHUNK * DINNER * DSTATE];

// bf16 split-GEMM operands, stored [hi | lo] along K (row stride 2K)
__device__ __nv_bfloat16 g_Xbig [NTOK * 2 * DMODEL];
__device__ __nv_bfloat16 g_W1big[(2 * DINNER) * 2 * DMODEL];
__device__ __nv_bfloat16 g_Ybig [NTOK * 2 * DINNER];
__device__ __nv_bfloat16 g_W2big[DMODEL * 2 * DINNER];

// ---------------- helpers ----------------
__device__ __forceinline__ uint32_t smem_u32(const void* p) {
    return (uint32_t)__cvta_generic_to_shared(p);
}
__device__ __forceinline__ void ldsm_x4(uint32_t& r0, uint32_t& r1,
                                        uint32_t& r2, uint32_t& r3, uint32_t addr) {
    asm volatile("ldmatrix.sync.aligned.m8n8.x4.shared.b16 {%0,%1,%2,%3}, [%4];"
                 : "=r"(r0), "=r"(r1), "=r"(r2), "=r"(r3) : "r"(addr));
}
__device__ __forceinline__ void mma_bf16(float* c, const uint32_t* a, const uint32_t* b) {
    asm volatile("mma.sync.aligned.m16n8k16.row.col.f32.bf16.bf16.f32 "
                 "{%0,%1,%2,%3}, {%4,%5,%6,%7}, {%8,%9}, {%0,%1,%2,%3};"
                 : "+f"(c[0]), "+f"(c[1]), "+f"(c[2]), "+f"(c[3])
                 : "r"(a[0]), "r"(a[1]), "r"(a[2]), "r"(a[3]), "r"(b[0]), "r"(b[1]));
}
__device__ __forceinline__ void cpasync16(uint32_t dst, const void* src) {
    asm volatile("cp.async.cg.shared.global [%0], [%1], 16;" :: "r"(dst), "l"(src));
}
__device__ __forceinline__ void cp_commit() {
    asm volatile("cp.async.commit_group;" ::: "memory");
}
template<int NWAIT>
__device__ __forceinline__ void cp_wait() {
    asm volatile("cp.async.wait_group %0;" :: "n"(NWAIT) : "memory");
}
__device__ __forceinline__ int warp_max(int v) {
#pragma unroll
    for (int off = 16; off > 0; off >>= 1)
        v = max(v, __shfl_xor_sync(0xffffffffu, v, off));
    return v;
}

// ---------------- bf16 tensor-core GEMM (mma.sync, 5-stage cp.async) -------
// C[M,N] = A'[M,3K] * B'[N,3K]^T with A' = [ah|al|ah], B' = [bh|bh|bl],
// A,B stored as [hi|lo] (row stride 2K); phase offsets recreate the triple.
#define BKP 40
#define GST_BYTES (128 * BKP * 2 * 2)     // 20480
#define GSTAGES   5
#define GSMEM_TOTAL (GSTAGES * GST_BYTES) // 102400

__global__ __launch_bounds__(256, 2)
void gemm_mma(const __nv_bfloat16* __restrict__ A,
              const __nv_bfloat16* __restrict__ B,
              float* __restrict__ C, int N, int K1)
{
    extern __shared__ char smem[];
    const int tid  = threadIdx.x;
    const int warp = tid >> 5, lane = tid & 31;
    const int wm = (warp & 3) << 5;
    const int wn = (warp >> 2) << 6;
    const size_t bM = (size_t)blockIdx.y * 128;
    const size_t bN = (size_t)blockIdx.x * 128;
    const int kt1 = K1 >> 5;
    const int KT  = 3 * kt1;
    const size_t lda = 2 * (size_t)K1;

    float acc[2][8][4];
#pragma unroll
    for (int i = 0; i < 2; i++)
#pragma unroll
        for (int j = 0; j < 8; j++)
#pragma unroll
            for (int q = 0; q < 4; q++) acc[i][j][q] = 0.f;

    const int ldr  = tid >> 2;       // 0..63
    const int slot = tid & 3;        // 0..3 (8 bf16 each)

    auto load_stage = [&](int s, int ktAbs) {
        int ph = (ktAbs >= 2 * kt1) ? 2 : ((ktAbs >= kt1) ? 1 : 0);
        int kk = (ktAbs - ph * kt1) << 5;
        int offA = (ph == 1) ? K1 : 0;
        int offB = (ph == 2) ? K1 : 0;
        char* sA = smem + s * GST_BYTES;
        char* sB = sA + 128 * BKP * 2;
        uint32_t da = smem_u32(sA) + (uint32_t)(ldr * BKP + slot * 8) * 2;
        uint32_t db = smem_u32(sB) + (uint32_t)(ldr * BKP + slot * 8) * 2;
        const __nv_bfloat16* ga = A + (bM + ldr) * lda + offA + kk + slot * 8;
        const __nv_bfloat16* gb = B + (bN + ldr) * lda + offB + kk + slot * 8;
        cpasync16(da, ga);
        cpasync16(da + 64 * BKP * 2, ga + 64 * lda);
        cpasync16(db, gb);
        cpasync16(db + 64 * BKP * 2, gb + 64 * lda);
    };

    load_stage(0, 0); cp_commit();
    load_stage(1, 1); cp_commit();
    load_stage(2, 2); cp_commit();
    load_stage(3, 3); cp_commit();

    const int lrow  = lane & 15;
    const int lcolo = (lane >> 4) << 3;

    for (int kt = 0; kt < KT; kt++) {
        cp_wait<3>();
        __syncthreads();
        if (kt + 4 < KT) load_stage((kt + 4) % GSTAGES, kt + 4);
        cp_commit();

        char* sS = smem + (kt % GSTAGES) * GST_BYTES;
        __nv_bfloat16 (*As)[BKP] = (__nv_bfloat16(*)[BKP])sS;
        __nv_bfloat16 (*Bs)[BKP] = (__nv_bfloat16(*)[BKP])(sS + 128 * BKP * 2);
#pragma unroll
        for (int kk = 0; kk < 32; kk += 16) {
            uint32_t af[2][4], bf[8][2];
#pragma unroll
            for (int i = 0; i < 2; i++)
                ldsm_x4(af[i][0], af[i][1], af[i][2], af[i][3],
                        smem_u32(&As[wm + i * 16 + lrow][kk + lcolo]));
#pragma unroll
            for (int j = 0; j < 4; j++) {
                uint32_t r0, r1, r2, r3;
                ldsm_x4(r0, r1, r2, r3,
                        smem_u32(&Bs[wn + j * 16 + lrow][kk + lcolo]));
                bf[2 * j][0] = r0; bf[2 * j + 1][0] = r1;
                bf[2 * j][1] = r2; bf[2 * j + 1][1] = r3;
            }
#pragma unroll
            for (int i = 0; i < 2; i++)
#pragma unroll
                for (int j = 0; j < 8; j++)
                    mma_bf16(acc[i][j], af[i], bf[j]);
        }
    }

#pragma unroll
    for (int i = 0; i < 2; i++) {
        const size_t rbase = bM + wm + i * 16 + (lane >> 2);
#pragma unroll
        for (int j = 0; j < 8; j++) {
            const size_t col = bN + wn + j * 8 + (lane & 3) * 2;
            *(float2*)&C[rbase * N + col]       = make_float2(acc[i][j][0], acc[i][j][1]);
            *(float2*)&C[(rbase + 8) * N + col] = make_float2(acc[i][j][2], acc[i][j][3]);
        }
    }
}

// ---------------- fp32 -> bf16 [hi|lo] pack ----------------
__global__ __launch_bounds__(256)
void pack2_kernel(const float* __restrict__ src, __nv_bfloat16* __restrict__ dst,
                  int K)
{
    const int g = blockIdx.x * 256 + threadIdx.x;
    const int kq = K >> 2;
    const int r = g / kq;
    const int k4 = (g - r * kq) << 2;
    float4 v = *(const float4*)(src + (size_t)r * K + k4);
    float vv[4] = {v.x, v.y, v.z, v.w};
    __nv_bfloat16 h[4], l[4];
#pragma unroll
    for (int i = 0; i < 4; i++) {
        h[i] = __float2bfloat16(vv[i]);
        l[i] = __float2bfloat16(vv[i] - __bfloat162float(h[i]));
    }
    __nv_bfloat16* base = dst + (size_t)r * 2 * K;
    *(uint2*)&base[k4]     = *(uint2*)h;
    *(uint2*)&base[K + k4] = *(uint2*)l;
}

// ---------------- y gating + bf16 [hi|lo] pack (fused) ----------------
__global__ __launch_bounds__(256)
void pack2y_kernel()
{
    const int g = blockIdx.x * 256 + threadIdx.x;        // NTOK*DINNER/4
    const int m  = g >> 9;                               // DINNER/4 = 512
    const int k4 = (g & 511) << 2;
    float4 yv = *(const float4*)(g_y + (size_t)m * DINNER + k4);
    float4 zv = *(const float4*)(g_xz + (size_t)m * (2 * DINNER) + DINNER + k4);
    float yy[4] = {yv.x, yv.y, yv.z, yv.w};
    float zz[4] = {zv.x, zv.y, zv.z, zv.w};
    __nv_bfloat16 h[4], l[4];
#pragma unroll
    for (int i = 0; i < 4; i++) {
        float sig = 1.f / (1.f + __expf(-zz[i]));
        float gv = yy[i] * zz[i] * sig;
        h[i] = __float2bfloat16(gv);
        l[i] = __float2bfloat16(gv - __bfloat162float(h[i]));
    }
    __nv_bfloat16* base = g_Ybig + (size_t)m * 2 * DINNER;
    *(uint2*)&base[k4]          = *(uint2*)h;
    *(uint2*)&base[DINNER + k4] = *(uint2*)l;
}

// ---------------- conv1d + silu + x_proj partials (D-split) ----------------
#define CT   16
#define DC   256
#define DSPLIT 2
#define DPB  (DINNER / DSPLIT)   // 1024
#define SXPP 260
#define CPSMEM ((CT * DC + 33 * SXPP + CT * 33) * 4)

__global__ __launch_bounds__(256)
void conv_proj4(const float* __restrict__ conv_w,
                const float* __restrict__ conv_b,
                const float* __restrict__ xpw)    // (33, 2048)
{
    extern __shared__ float sm[];
    float* sxc = sm;                    // [CT][DC]
    float* sxp = sm + CT * DC;          // [33][SXPP]
    float* sps = sxp + 33 * SXPP;       // [CT][33]

    const int b  = blockIdx.z;
    const int ds = blockIdx.y;
    const int t0 = blockIdx.x * CT;
    const int tid = threadIdx.x;
    const int warp = tid >> 5, lane = tid & 31;

    float acc[2]   = {0.f, 0.f};
    float acc32[2] = {0.f, 0.f};

    for (int d0 = ds * DPB; d0 < ds * DPB + DPB; d0 += DC) {
        // phase A: conv + silu, rolling window per thread (fixed d, t varies)
        {
            const int d = d0 + tid;
            const float cw0 = conv_w[d * DCONV + 0];
            const float cw1 = conv_w[d * DCONV + 1];
            const float cw2 = conv_w[d * DCONV + 2];
            const float cw3 = conv_w[d * DCONV + 3];
            const float cb  = conv_b[d];
            const size_t rb = (size_t)(b * SEQLEN + t0) * (2 * DINNER) + d;
            float xm3 = (t0 >= 3) ? g_xz[rb - 3 * (2 * DINNER)] : 0.f;
            float xm2 = (t0 >= 2) ? g_xz[rb - 2 * (2 * DINNER)] : 0.f;
            float xm1 = (t0 >= 1) ? g_xz[rb - 1 * (2 * DINNER)] : 0.f;
#pragma unroll
            for (int k = 0; k < CT; k++) {
                float xv = g_xz[rb + (size_t)k * (2 * DINNER)];
                float cv = cb;
                cv = fmaf(cw0, xm3, cv); cv = fmaf(cw1, xm2, cv);
                cv = fmaf(cw2, xm1, cv); cv = fmaf(cw3, xv,  cv);
                xm3 = xm2; xm2 = xm1; xm1 = xv;
                sxc[k * DC + tid] = cv / (1.f + __expf(-cv));
            }
        }
        // stage xpw chunk
#pragma unroll
        for (int m = 0; m < 33; m++)
            sxp[m * SXPP + tid] = xpw[m * DINNER + d0 + tid];
        __syncthreads();

        // phase B: per-warp 2 tokens x 32 lanes(j)
        const float* xr0 = sxc + (warp * 2 + 0) * DC;
        const float* xr1 = sxc + (warp * 2 + 1) * DC;
        const float* wvp = sxp + lane * SXPP;
#pragma unroll 8
        for (int dd0 = 0; dd0 < DC; dd0 += 4) {
            float4 w4 = *(const float4*)(wvp + dd0);
            float4 x0 = *(const float4*)(xr0 + dd0);
            float4 x1 = *(const float4*)(xr1 + dd0);
            acc[0] = fmaf(x0.x, w4.x, acc[0]); acc[0] = fmaf(x0.y, w4.y, acc[0]);
            acc[0] = fmaf(x0.z, w4.z, acc[0]); acc[0] = fmaf(x0.w, w4.w, acc[0]);
            acc[1] = fmaf(x1.x, w4.x, acc[1]); acc[1] = fmaf(x1.y, w4.y, acc[1]);
            acc[1] = fmaf(x1.z, w4.z, acc[1]); acc[1] = fmaf(x1.w, w4.w, acc[1]);
        }
        const float* w32 = sxp + 32 * SXPP;
#pragma unroll
        for (int dd = lane; dd < DC; dd += 32) {
            float wvv = w32[dd];
            acc32[0] = fmaf(xr0[dd], wvv, acc32[0]);
            acc32[1] = fmaf(xr1[dd], wvv, acc32[1]);
        }
        __syncthreads();
    }
#pragma unroll
    for (int tk = 0; tk < 2; tk++) {
#pragma unroll
        for (int off = 16; off > 0; off >>= 1)
            acc32[tk] += __shfl_down_sync(0xffffffffu, acc32[tk], off);
    }
#pragma unroll
    for (int tk = 0; tk < 2; tk++) {
        sps[(warp * 2 + tk) * 33 + lane] = acc[tk];
        if (lane == 0) sps[(warp * 2 + tk) * 33 + 32] = acc32[tk];
    }
    __syncthreads();

    // write partials
    for (int e = tid; e < CT * 33; e += 256) {
        const int tt = e / 33, j = e - tt * 33;
        g_xpp[((size_t)ds * NTOK + b * SEQLEN + t0 + tt) * 33 + j] = sps[tt * 33 + j];
    }
}

// ---------------- reduce x_proj partials -> xp0 / B / C ----------------
__global__ __launch_bounds__(256)
void xps_reduce()
{
    const int i = blockIdx.x * 256 + threadIdx.x;   // NTOK*33
    if (i >= NTOK * 33) return;
    const int m = i / 33, j = i - m * 33;
    float v = g_xpp[(size_t)m * 33 + j] + g_xpp[(size_t)NTOK * 33 + m * 33 + j];
    if (j == 0)       g_xp0[m] = v;
    else if (j <= 16) g_Bb[m * DSTATE + (j - 1)] = v;
    else              g_Cc[m * DSTATE + (j - 17)] = v;
}

// ---------------- scan pass A: fused conv/silu/softplus + local recurrence --
__global__ __launch_bounds__(256)
void scanA_kernel(const float* __restrict__ A_log,
                  const float* __restrict__ D_param,
                  const float* __restrict__ conv_w,
                  const float* __restrict__ conv_b,
                  const float* __restrict__ dt_w,
                  const float* __restrict__ dt_b)
{
    const int d = blockIdx.x * 256 + threadIdx.x;
    const int c = blockIdx.y;
    const int b = blockIdx.z;
    const int m0 = b * SEQLEN + c * CHUNK;

    __shared__ float Bs[CHUNK * DSTATE];
    __shared__ float Cs[CHUNK * DSTATE];
    __shared__ float sxp0[CHUNK];
    {
        const float4* gb = (const float4*)(g_Bb + (size_t)m0 * DSTATE);
        const float4* gc = (const float4*)(g_Cc + (size_t)m0 * DSTATE);
        for (int i = threadIdx.x; i < CHUNK * DSTATE / 4; i += 256) {
            ((float4*)Bs)[i] = gb[i];
            ((float4*)Cs)[i] = gc[i];
        }
        sxp0[threadIdx.x] = g_xp0[m0 + threadIdx.x];
    }

    float Areg[DSTATE];
#pragma unroll
    for (int s = 0; s < DSTATE; s++) Areg[s] = -expf(A_log[s]);
    const float Dd  = D_param[d];
    const float cw0 = conv_w[d * DCONV + 0];
    const float cw1 = conv_w[d * DCONV + 1];
    const float cw2 = conv_w[d * DCONV + 2];
    const float cw3 = conv_w[d * DCONV + 3];
    const float cb  = conv_b[d];
    const float dw  = dt_w[d];
    const float db  = dt_b[d];
    __syncthreads();

    const size_t rb = (size_t)m0 * (2 * DINNER) + d;
    float xm3 = (c > 0) ? g_xz[rb - 3 * (2 * DINNER)] : 0.f;
    float xm2 = (c > 0) ? g_xz[rb - 2 * (2 * DINNER)] : 0.f;
    float xm1 = (c > 0) ? g_xz[rb - 1 * (2 * DINNER)] : 0.f;

    float L[DSTATE], W[DSTATE], H[DSTATE];
#pragma unroll
    for (int s = 0; s < DSTATE; s++) { L[s] = 0.f; W[s] = 0.f; H[s] = 0.f; }

    int nalive = DSTATE;
    for (int t = 0; t < CHUNK; t++) {
        // conv + silu (rolling window)
        float xv = g_xz[rb + (size_t)t * (2 * DINNER)];
        float cv = cb;
        cv = fmaf(cw0, xm3, cv); cv = fmaf(cw1, xm2, cv);
        cv = fmaf(cw2, xm1, cv); cv = fmaf(cw3, xv,  cv);
        xm3 = xm2; xm2 = xm1; xm1 = xv;
        const float xcv = cv / (1.f + __expf(-cv));
        // delta = softplus(xp0 * dt_w + dt_b)
        const float u  = fmaf(sxp0[t], dw, db);
        const float dl = fmaxf(u, 0.f) + log1pf(__expf(-fabsf(u)));
        const float dx = dl * xcv;
        float y = Dd * xcv;
        int cnt = 0;
#pragma unroll
        for (int s = 0; s < DSTATE; s++) {
            if (s < nalive) {
                float e = __expf(L[s]);                   // A_cum_sh
                float bx = dx * Bs[t * DSTATE + s];
                W[s] += __fdividef(bx, fmaxf(e, EPSF));
                float h = e * W[s];
                H[s] = h;
                y = fmaf(Cs[t * DSTATE + s], h, y);
                L[s] += fmaxf(dl * Areg[s], LNEPS);
                if (L[s] > LDEAD) cnt = s + 1;
            }
        }
        g_y[(size_t)(m0 + t) * DINNER + d] = y;
        nalive = warp_max(cnt);
    }
    const size_t o = ((size_t)(b * NCHUNK + c) * DINNER + d) * DSTATE;
#pragma unroll
    for (int s = 0; s < DSTATE; s++) {
        g_hloc[o + s] = H[s];
        g_Atot[o + s] = __expf(L[s]);
    }
}

// ---------------- chunk carry ----------------
__global__ __launch_bounds__(256)
void carry_kernel()
{
    const int i = blockIdx.x * 256 + threadIdx.x;
    const int s = i & (DSTATE - 1);
    const int d = (i >> 4) & (DINNER - 1);
    const int b = i >> 15;
    float h = 0.f;
#pragma unroll
    for (int c = 0; c < NCHUNK; c++) {
        const size_t o = ((size_t)(b * NCHUNK + c) * DINNER + d) * DSTATE + s;
        g_h0[o] = h;
        h = g_hloc[o] + h * g_Atot[o];
    }
}

// ---------------- scan pass B: y += C·h0·A_cum (delta recomputed) -----------
__global__ __launch_bounds__(256)
void scanB_kernel(const float* __restrict__ A_log,
                  const float* __restrict__ dt_w,
                  const float* __restrict__ dt_b)
{
    const int d = blockIdx.x * 256 + threadIdx.x;
    const int c = blockIdx.y;
    const int b = blockIdx.z;
    const int m0 = b * SEQLEN + c * CHUNK;

    __shared__ float Cs[CHUNK * DSTATE];
    __shared__ float sxp0[CHUNK];
    {
        const float4* gc = (const float4*)(g_Cc + (size_t)m0 * DSTATE);
        for (int i = threadIdx.x; i < CHUNK * DSTATE / 4; i += 256)
            ((float4*)Cs)[i] = gc[i];
        sxp0[threadIdx.x] = g_xp0[m0 + threadIdx.x];
    }

    float Areg[DSTATE], h0r[DSTATE], L[DSTATE];
    const size_t o = ((size_t)(b * NCHUNK + c) * DINNER + d) * DSTATE;
    int cnt = 0;
#pragma unroll
    for (int s = 0; s < DSTATE; s++) {
        Areg[s] = -expf(A_log[s]);
        h0r[s] = g_h0[o + s];
        L[s] = 0.f;
        if (fabsf(h0r[s]) > HTHRESH) cnt = s + 1;
    }
    const float dw = dt_w[d];
    const float db = dt_b[d];
    __syncthreads();
    int nalive = warp_max(cnt);

    for (int t = 0; t < CHUNK && nalive > 0; t++) {
        const float u  = fmaf(sxp0[t], dw, db);
        const float dl = fmaxf(u, 0.f) + log1pf(__expf(-fabsf(u)));
        float corr = 0.f;
        int c2 = 0;
#pragma unroll
        for (int s = 0; s < DSTATE; s++) {
            if (s < nalive) {
                L[s] += fmaxf(dl * Areg[s], LNEPS);
                corr = fmaf(h0r[s] * Cs[t * DSTATE + s], __expf(L[s]), corr);
                if (L[s] > LDEAD && fabsf(h0r[s]) > HTHRESH) c2 = s + 1;
            }
        }
        g_y[(size_t)(m0 + t) * DINNER + d] += corr;
        nalive = warp_max(c2);
    }
}

// ---------------- launch ----------------
extern "C" void kernel_launch(void* const* d_in, const int* in_sizes, int n_in,
                              void* d_out, int out_size)
{
    const float* x       = (const float*)d_in[0];
    const float* in_w    = (const float*)d_in[1];
    const float* conv_w  = (const float*)d_in[2];
    const float* conv_b  = (const float*)d_in[3];
    const float* xpw     = (const float*)d_in[4];
    const float* dt_w    = (const float*)d_in[5];
    const float* dt_b    = (const float*)d_in[6];
    const float* A_log   = (const float*)d_in[7];
    const float* D_param = (const float*)d_in[8];
    const float* out_w   = (const float*)d_in[9];
    float* out           = (float*)d_out;

    float *p_xz;
    __nv_bfloat16 *p_Xbig, *p_W1big, *p_Ybig, *p_W2big;
    cudaGetSymbolAddress((void**)&p_xz,    g_xz);
    cudaGetSymbolAddress((void**)&p_Xbig,  g_Xbig);
    cudaGetSymbolAddress((void**)&p_W1big, g_W1big);
    cudaGetSymbolAddress((void**)&p_Ybig,  g_Ybig);
    cudaGetSymbolAddress((void**)&p_W2big, g_W2big);

    cudaFuncSetAttribute(gemm_mma, cudaFuncAttributeMaxDynamicSharedMemorySize,
                         GSMEM_TOTAL);
    cudaFuncSetAttribute(conv_proj4, cudaFuncAttributeMaxDynamicSharedMemorySize,
                         CPSMEM);

    // launches 0-4: packs (gemm1 lands at ncu skip index 5)
    pack2_kernel<<<(NTOK * DMODEL / 4) / 256, 256>>>(x, p_Xbig, DMODEL);
    pack2_kernel<<<(DINNER * DMODEL / 4) / 256, 256>>>(in_w, p_W1big, DMODEL);
    pack2_kernel<<<(DINNER * DMODEL / 4) / 256, 256>>>(
        in_w + (size_t)DINNER * DMODEL, p_W1big + (size_t)DINNER * 2 * DMODEL, DMODEL);
    pack2_kernel<<<((DMODEL / 2) * DINNER / 4) / 256, 256>>>(out_w, p_W2big, DINNER);
    pack2_kernel<<<((DMODEL / 2) * DINNER / 4) / 256, 256>>>(
        out_w + (size_t)(DMODEL / 2) * DINNER, p_W2big + (size_t)(DMODEL / 2) * 2 * DINNER, DINNER);

    // 5) xz = x @ in_proj_w^T  (M=4096, N=4096, K1=1024 -> 3 phases)
    {
        dim3 grid((2 * DINNER) / 128, NTOK / 128);
        gemm_mma<<<grid, 256, GSMEM_TOTAL>>>(p_Xbig, p_W1big, p_xz, 2 * DINNER, DMODEL);
    }
    // 6) conv + silu + x_proj partials (D-split)
    {
        dim3 grid(SEQLEN / CT, DSPLIT, BATCH);
        conv_proj4<<<grid, 256, CPSMEM>>>(conv_w, conv_b, xpw);
    }
    // 7) reduce partials -> xp0 / B / C
    xps_reduce<<<(NTOK * 33 + 255) / 256, 256>>>();
    // 8) fused local scan
    {
        dim3 grid(DINNER / 256, NCHUNK, BATCH);
        scanA_kernel<<<grid, 256>>>(A_log, D_param, conv_w, conv_b, dt_w, dt_b);
    }
    // 9) chunk carry
    carry_kernel<<<(BATCH * DINNER * DSTATE) / 256, 256>>>();
    // 10) carry correction (sparse)
    {
        dim3 grid(DINNER / 256, NCHUNK, BATCH);
        scanB_kernel<<<grid, 256>>>(A_log, dt_w, dt_b);
    }
    // 11) gate + pack y
    pack2y_kernel<<<(NTOK * DINNER / 4) / 256, 256>>>();
    // 12) out = y @ out_proj_w^T
    {
        dim3 grid(DMODEL / 128, NTOK / 128);
        gemm_mma<<<grid, 256, GSMEM_TOTAL>>>(p_Ybig, p_W2big, out, DMODEL, DINNER);
    }
}